// round 5
// baseline (speedup 1.0000x reference)
#include <cuda_runtime.h>
#include <math.h>

#define Hh 2
#define Bb 8
#define Nn 2048
#define Dd 64
#define Qq 16
#define Cc 129
#define C8v 16
#define Kk 8192
#define VP 132
#define NEGV (-9.0e15f)
#define NROW (Bb*Nn)
#define RT 64
#define MT 64
#define NTILE (Nn/MT)
#define AT 512   // attn threads

// ---------------- packed f32x2 helpers (Blackwell) ----------------
typedef unsigned long long u64t;
#define PACK2(out, lo, hi) \
    asm("mov.b64 %0, {%1, %2};" : "=l"(out) : "f"(lo), "f"(hi))
#define UNPACK2(lo, hi, in) \
    asm("mov.b64 {%0, %1}, %2;" : "=f"(lo), "=f"(hi) : "l"(in))
#define FMA2(d, a, b, c) \
    asm("fma.rn.f32x2 %0, %1, %2, %3;" : "=l"(d) : "l"(a), "l"(b), "l"(c))
#define MUL2(d, a, b) \
    asm("mul.rn.f32x2 %0, %1, %2;" : "=l"(d) : "l"(a), "l"(b))

// ---------------- device scratch ----------------
__device__ float g_q[Hh*NROW*C8v];
__device__ float g_k[Hh*NROW*C8v];
__device__ float g_v[Hh*NROW*VP];
__device__ float g_comb[NROW*VP];
__device__ float g_u[Kk*Dd];
__device__ float g_hsel[Kk*Dd];
__device__ float g_cx[Kk*Dd];
__device__ int   g_batch_flag[Bb];
__device__ int   g_tile_flag[NROW/RT];

// ---------------- cp.async helpers ----------------
__device__ __forceinline__ unsigned smem_u32(const void* p) {
    return (unsigned)__cvta_generic_to_shared(p);
}
__device__ __forceinline__ void cp16(void* dst, const void* src) {
    asm volatile("cp.async.cg.shared.global [%0], [%1], 16;\n"
                 :: "r"(smem_u32(dst)), "l"(src));
}
__device__ __forceinline__ void cp_commit() { asm volatile("cp.async.commit_group;\n"); }
template<int N> __device__ __forceinline__ void cp_wait() {
    asm volatile("cp.async.wait_group %0;\n" :: "n"(N));
}

// ---------------- flags ----------------
__global__ void flag_zero_kernel() {
    int t = threadIdx.x;
    if (t < Bb) g_batch_flag[t] = 0;
    for (int i = t; i < NROW/RT; i += 256) g_tile_flag[i] = 0;
}
__global__ void flag_mark_kernel(const int* __restrict__ nodes) {
    int i = blockIdx.x * 256 + threadIdx.x;
    if (i < Kk) {
        int row = nodes[i];
        g_tile_flag[row >> 6] = 1;
        g_batch_flag[row >> 11] = 1;
    }
}

// =================== 1) QKV projection ===================
struct ProjSmem {
    float comb[Cc][36];
    float W[Cc][VP];
    float bias[VP];
};

__global__ void proj_kernel(const float* __restrict__ x, const float* __restrict__ h,
                            const float* __restrict__ Wq, const float* __restrict__ bq,
                            const float* __restrict__ Wk, const float* __restrict__ bk,
                            const float* __restrict__ Wv, const float* __restrict__ bv) {
    extern __shared__ char sm_raw[];
    ProjSmem& sm = *reinterpret_cast<ProjSmem*>(sm_raw);
    const int t = threadIdx.x;
    const int row0 = blockIdx.x * 32;
    if (!g_batch_flag[row0 >> 11]) return;
    const int y = blockIdx.y;

    for (int idx = t; idx < 32 * Cc; idx += 256) {
        int r = idx / Cc, c = idx % Cc;
        int row = row0 + r;
        float v = (c < 65) ? x[row * 65 + c] : h[row * 64 + (c - 65)];
        sm.comb[c][r] = v;
    }
    if (y == 0) {
        for (int idx = t; idx < Cc * 64; idx += 256) {
            int c = idx / 64, o = idx % 64;
            float w;
            if (o < 32)      w = Wq[((o >> 4) * Cc + c) * C8v + (o & 15)];
            else { int o2 = o - 32; w = Wk[((o2 >> 4) * Cc + c) * C8v + (o2 & 15)]; }
            sm.W[c][o] = w;
        }
        if (t < 64) {
            float b;
            if (t < 32)      b = bq[(t >> 4) * C8v + (t & 15)];
            else { int o2 = t - 32; b = bk[(o2 >> 4) * C8v + (o2 & 15)]; }
            sm.bias[t] = b;
        }
    } else {
        int hh = y - 1;
        for (int idx = t; idx < Cc * VP; idx += 256) {
            int c = idx / VP, o = idx % VP;
            sm.W[c][o] = (o < Cc) ? Wv[(hh * Cc + c) * Cc + o] : 0.f;
        }
        for (int o = t; o < VP; o += 256) sm.bias[o] = (o < Cc) ? bv[hh * Cc + o] : 0.f;
    }
    __syncthreads();

    if (y == 0) {
        int r = t >> 3, og = t & 7;
        int c0 = og * 8;
        float acc[8];
#pragma unroll
        for (int j = 0; j < 8; j++) acc[j] = 0.f;
        for (int c = 0; c < Cc; c++) {
            float a = sm.comb[c][r];
#pragma unroll
            for (int j = 0; j < 8; j++) acc[j] += a * sm.W[c][c0 + j];
        }
        int row = row0 + r;
#pragma unroll
        for (int j = 0; j < 8; j++) {
            int o = c0 + j;
            float val = acc[j] + sm.bias[o];
            if (o < 32) {
                g_q[(((o >> 4) * NROW) + row) * C8v + (o & 15)] = val;
            } else {
                int o2 = o - 32;
                g_k[(((o2 >> 4) * NROW) + row) * C8v + (o2 & 15)] = val;
            }
        }
    } else {
        int hh = y - 1;
        int r = t >> 3, og = t & 7;
        int c0 = og * 16;
        int xcol = 128 + og;
        float acc[17];
#pragma unroll
        for (int j = 0; j < 17; j++) acc[j] = 0.f;
        for (int c = 0; c < Cc; c++) {
            float a = sm.comb[c][r];
#pragma unroll
            for (int j = 0; j < 16; j++) acc[j] += a * sm.W[c][c0 + j];
            if (og < 4) acc[16] += a * sm.W[c][xcol];
        }
        int row = row0 + r;
        float* dst = &g_v[((hh * NROW) + row) * VP];
#pragma unroll
        for (int j = 0; j < 16; j++) dst[c0 + j] = acc[j] + sm.bias[c0 + j];
        if (og < 4) dst[xcol] = acc[16] + sm.bias[xcol];
    }
}

// =================== 2) attention (512 threads, MT=64, double-buffered) ===================
struct AttnSmem {
    float v[2][Hh][MT][VP];      // 135168 B
    float k[2][Hh][MT][C8v];     //  16384 B
    int   adj[2][RT][68];        //  34816 B
    float p[Hh][MT][RT];         //  32768 B
    float rmax[Hh][RT];
    float rsum[Hh][RT];
    float fac[Hh][RT];
};                               // ~220 KB

__device__ __forceinline__ void attn_prefetch(AttnSmem& sm, int buf, int b, int row0,
                                              int m0, const int* __restrict__ adjg, int t) {
    for (int idx = t; idx < Hh * MT * 33; idx += AT) {
        int h_ = idx / (MT * 33), rem = idx % (MT * 33), m = rem / 33, c4 = rem % 33;
        cp16(&sm.v[buf][h_][m][c4 * 4],
             &g_v[((h_ * NROW) + b * Nn + m0 + m) * VP + c4 * 4]);
    }
    for (int idx = t; idx < Hh * MT * 4; idx += AT) {
        int h_ = idx / (MT * 4), rem = idx % (MT * 4), m = rem >> 2, d4 = rem & 3;
        cp16(&sm.k[buf][h_][m][d4 * 4],
             &g_k[((h_ * NROW) + b * Nn + m0 + m) * C8v + d4 * 4]);
    }
    for (int idx = t; idx < RT * 16; idx += AT) {
        int r = idx >> 4, c4 = idx & 15;
        cp16(&sm.adj[buf][r][c4 * 4],
             &adjg[(b * Nn + row0 + r) * Nn + m0 + c4 * 4]);
    }
}

__global__ void __launch_bounds__(AT, 1) attn_kernel(const int* __restrict__ adjg) {
    extern __shared__ char sm_raw[];
    AttnSmem& sm = *reinterpret_cast<AttnSmem*>(sm_raw);
    const int t = threadIdx.x;
    const int b = blockIdx.y;
    const int row0 = blockIdx.x * RT;
    if (!g_tile_flag[(b * Nn + row0) >> 6]) return;

    const int hh = t >> 8;              // head for scores & PV
    const int t8 = t & 255;
    // scores/softmax: (hh, s_r), quarter of keys
    const int s_r = t8 >> 2, s_q = t8 & 3;
    // PV: 4 rows x 8 cols
    const int r0 = (t8 >> 4) * 4, c0 = (t8 & 15) * 8;
    // col-128: threads 0..127
    const int x_hh = t >> 6, x_r = t & 63;

    float qreg[16];
    {
        const float4* qsrc = (const float4*)&g_q[((hh * NROW) + b * Nn + row0 + s_r) * C8v];
#pragma unroll
        for (int j = 0; j < 4; j++) {
            float4 qq = qsrc[j];
            qreg[4 * j] = qq.x; qreg[4 * j + 1] = qq.y;
            qreg[4 * j + 2] = qq.z; qreg[4 * j + 3] = qq.w;
        }
    }
    if (t < 128) { sm.rmax[x_hh][x_r] = -INFINITY; sm.rsum[x_hh][x_r] = 0.f; }

    u64t acc2[4][4];   // [row][col-pair]
#pragma unroll
    for (int i = 0; i < 4; i++)
#pragma unroll
        for (int j = 0; j < 4; j++) acc2[i][j] = 0ull;
    float acc128 = 0.f;

    attn_prefetch(sm, 0, b, row0, 0, adjg, t);
    cp_commit();

    for (int mt = 0; mt < NTILE; mt++) {
        const int buf = mt & 1;
        if (mt + 1 < NTILE) attn_prefetch(sm, buf ^ 1, b, row0, (mt + 1) * MT, adjg, t);
        cp_commit();
        cp_wait<1>();
        __syncthreads();

        // ---- scores: 16 keys per thread ----
        {
#pragma unroll 4
            for (int i = 0; i < 16; i++) {
                int m = s_q * 16 + i;
                const float4* k4 = (const float4*)&sm.k[buf][hh][m][0];
                float s = 0.f;
#pragma unroll
                for (int d4 = 0; d4 < 4; d4++) {
                    float4 kk = k4[d4];
                    s += qreg[4 * d4] * kk.x + qreg[4 * d4 + 1] * kk.y
                       + qreg[4 * d4 + 2] * kk.z + qreg[4 * d4 + 3] * kk.w;
                }
                s *= 0.25f;
                s = (s > 0.f) ? s : 0.2f * s;
                if (sm.adj[buf][s_r][m] == 0) s = NEGV;
                sm.p[hh][m][s_r] = s;
            }
        }
        __syncthreads();

        // ---- online softmax: 4 threads per (hh, row), 16 keys each ----
        {
            float tmax = -INFINITY;
#pragma unroll 4
            for (int j = 0; j < 16; j++)
                tmax = fmaxf(tmax, sm.p[hh][s_q * 16 + j][s_r]);
            tmax = fmaxf(tmax, __shfl_xor_sync(0xffffffffu, tmax, 1, 4));
            tmax = fmaxf(tmax, __shfl_xor_sync(0xffffffffu, tmax, 2, 4));
            float oldmax = sm.rmax[hh][s_r];
            float nmax = fmaxf(oldmax, tmax);
            float ssum = 0.f;
#pragma unroll 4
            for (int j = 0; j < 16; j++) {
                int m = s_q * 16 + j;
                float e = __expf(sm.p[hh][m][s_r] - nmax);
                sm.p[hh][m][s_r] = e;
                ssum += e;
            }
            ssum += __shfl_xor_sync(0xffffffffu, ssum, 1, 4);
            ssum += __shfl_xor_sync(0xffffffffu, ssum, 2, 4);
            if (s_q == 0) {
                float f = __expf(oldmax - nmax);
                sm.fac[hh][s_r] = f;
                sm.rsum[hh][s_r] = sm.rsum[hh][s_r] * f + ssum;
                sm.rmax[hh][s_r] = nmax;
            }
        }
        __syncthreads();

        // ---- PV accumulate (packed f32x2, 4 rows x 8 cols) ----
        {
#pragma unroll
            for (int i = 0; i < 4; i++) {
                float f = sm.fac[hh][r0 + i];
                u64t fd; PACK2(fd, f, f);
#pragma unroll
                for (int j = 0; j < 4; j++) MUL2(acc2[i][j], acc2[i][j], fd);
            }
            if (t < 128) acc128 *= sm.fac[x_hh][x_r];

#pragma unroll 4
            for (int m = 0; m < MT; m++) {
                float4 p0 = *(const float4*)&sm.p[hh][m][r0];
                float4 v0 = *(const float4*)&sm.v[buf][hh][m][c0];
                float4 v1 = *(const float4*)&sm.v[buf][hh][m][c0 + 4];
                u64t vv[4];
                PACK2(vv[0], v0.x, v0.y); PACK2(vv[1], v0.z, v0.w);
                PACK2(vv[2], v1.x, v1.y); PACK2(vv[3], v1.z, v1.w);
                float pv[4] = {p0.x, p0.y, p0.z, p0.w};
#pragma unroll
                for (int i = 0; i < 4; i++) {
                    u64t pd; PACK2(pd, pv[i], pv[i]);
#pragma unroll
                    for (int j = 0; j < 4; j++)
                        FMA2(acc2[i][j], pd, vv[j], acc2[i][j]);
                }
            }
            if (t < 128) {
#pragma unroll 4
                for (int m = 0; m < MT; m++)
                    acc128 += sm.p[x_hh][m][x_r] * sm.v[buf][x_hh][m][128];
            }
        }
        __syncthreads();
    }

    // ---- finalize: mean over heads ----
    float accf[4][8];
#pragma unroll
    for (int i = 0; i < 4; i++) {
        float inv = 0.5f / sm.rsum[hh][r0 + i];
#pragma unroll
        for (int j = 0; j < 4; j++) {
            float lo, hi;
            UNPACK2(lo, hi, acc2[i][j]);
            accf[i][2 * j] = lo * inv;
            accf[i][2 * j + 1] = hi * inv;
        }
    }

    float* osh = (float*)&sm.v[0][0][0][0];
    if (hh == 0) {
#pragma unroll
        for (int i = 0; i < 4; i++)
#pragma unroll
            for (int j = 0; j < 8; j++)
                osh[(r0 + i) * VP + (c0 + j)] = accf[i][j];
    }
    if (t < 64) osh[x_r * VP + 128] = acc128 * (0.5f / sm.rsum[0][x_r]);
    __syncthreads();
    if (hh == 1) {
#pragma unroll
        for (int i = 0; i < 4; i++)
#pragma unroll
            for (int j = 0; j < 8; j++)
                osh[(r0 + i) * VP + (c0 + j)] += accf[i][j];
    }
    if (t >= 64 && t < 128) osh[x_r * VP + 128] += acc128 * (0.5f / sm.rsum[1][x_r]);
    __syncthreads();

    for (int idx = t; idx < RT * Cc; idx += AT) {
        int r = idx / Cc, c = idx % Cc;
        g_comb[(b * Nn + row0 + r) * VP + c] = osh[r * VP + c];
    }
}

// =================== 3a) gates r, u, cand_x ===================
struct GateASmem {
    float sel[Cc][68];
    float qv[Qq][64];
    float W[2][Cc][64];
    int   nodes[64];
};

__global__ void __launch_bounds__(256, 2) gateA_kernel(
    const float* __restrict__ qv_g, const int* __restrict__ nodes,
    const float* __restrict__ x_g, const float* __restrict__ h_g,
    const float* __restrict__ W_r, const float* __restrict__ b_r,
    const float* __restrict__ W_u, const float* __restrict__ b_u,
    const float* __restrict__ W_c, const float* __restrict__ b_c) {
    extern __shared__ char sm_raw[];
    GateASmem& sm = *reinterpret_cast<GateASmem*>(sm_raw);
    const int t = threadIdx.x;
    const int k0 = blockIdx.x * 64;
    const int g = blockIdx.y;
    const float* W    = (g == 0) ? W_r : (g == 1) ? W_u : W_c;
    const float* bias = (g == 0) ? b_r : (g == 1) ? b_u : b_c;
    const int CN = (g == 2) ? 65 : Cc;
    const int NCH = CN * 16;

    if (t < 64) sm.nodes[t] = nodes[k0 + t];
    __syncthreads();
    if (g == 2) {
        for (int idx = t; idx < 64 * 65; idx += 256) {
            int r = idx / 65, c = idx % 65;
            sm.sel[c][r] = x_g[sm.nodes[r] * 65 + c];
        }
    } else {
        for (int idx = t; idx < 64 * Cc; idx += 256) {
            int r = idx / Cc, c = idx % Cc;
            sm.sel[c][r] = g_comb[sm.nodes[r] * VP + c];
        }
    }
    for (int idx = t; idx < 64 * Qq; idx += 256) {
        int r = idx / Qq, q = idx % Qq;
        sm.qv[q][r] = qv_g[(k0 + r) * Qq + q];
    }
    for (int idx = t; idx < NCH; idx += 256)
        cp16(&sm.W[0][idx / 16][(idx % 16) * 4], &W[(idx / 16) * 64 + (idx % 16) * 4]);
    cp_commit();

    const int rg = t >> 4, og = t & 15;
    const int r0 = rg * 4, o0 = og * 4;
    u64t acc2[4][2];
#pragma unroll
    for (int i = 0; i < 4; i++) { acc2[i][0] = 0ull; acc2[i][1] = 0ull; }

    for (int q = 0; q < Qq; q++) {
        const int buf = q & 1;
        if (q + 1 < Qq) {
            for (int idx = t; idx < NCH; idx += 256)
                cp16(&sm.W[buf ^ 1][idx / 16][(idx % 16) * 4],
                     &W[((q + 1) * Cc + idx / 16) * 64 + (idx % 16) * 4]);
        }
        cp_commit();
        cp_wait<1>();
        __syncthreads();

        u64t a2[4][2];
#pragma unroll
        for (int i = 0; i < 4; i++) { a2[i][0] = 0ull; a2[i][1] = 0ull; }
        for (int c = 0; c < CN; c++) {
            float4 a = *(const float4*)&sm.sel[c][r0];
            float4 w = *(const float4*)&sm.W[buf][c][o0];
            u64t wv0, wv1;
            PACK2(wv0, w.x, w.y); PACK2(wv1, w.z, w.w);
            float av[4] = {a.x, a.y, a.z, a.w};
#pragma unroll
            for (int i = 0; i < 4; i++) {
                u64t ad; PACK2(ad, av[i], av[i]);
                FMA2(a2[i][0], ad, wv0, a2[i][0]);
                FMA2(a2[i][1], ad, wv1, a2[i][1]);
            }
        }
        float4 qq = *(const float4*)&sm.qv[q][r0];
        float qvv[4] = {qq.x, qq.y, qq.z, qq.w};
#pragma unroll
        for (int i = 0; i < 4; i++) {
            u64t qd; PACK2(qd, qvv[i], qvv[i]);
            FMA2(acc2[i][0], qd, a2[i][0], acc2[i][0]);
            FMA2(acc2[i][1], qd, a2[i][1], acc2[i][1]);
        }
        __syncthreads();
    }

    float acc[4][4];
#pragma unroll
    for (int i = 0; i < 4; i++) {
        UNPACK2(acc[i][0], acc[i][1], acc2[i][0]);
        UNPACK2(acc[i][2], acc[i][3], acc2[i][1]);
    }
    for (int q = 0; q < Qq; q++) {
        float4 bb = *(const float4*)&bias[q * 64 + o0];
        float bv4[4] = {bb.x, bb.y, bb.z, bb.w};
        float4 qq = *(const float4*)&sm.qv[q][r0];
        float qvv[4] = {qq.x, qq.y, qq.z, qq.w};
#pragma unroll
        for (int i = 0; i < 4; i++)
#pragma unroll
            for (int j = 0; j < 4; j++) acc[i][j] += qvv[i] * bv4[j];
    }
#pragma unroll
    for (int i = 0; i < 4; i++) {
        int kidx = k0 + r0 + i;
#pragma unroll
        for (int j = 0; j < 4; j++) {
            int o = o0 + j;
            if (g == 0) {
                float z = 1.f / (1.f + __expf(-acc[i][j]));
                g_hsel[kidx * 64 + o] = z * h_g[sm.nodes[r0 + i] * 64 + o];
            } else if (g == 1) {
                g_u[kidx * 64 + o] = 1.f / (1.f + __expf(-acc[i][j]));
            } else {
                g_cx[kidx * 64 + o] = acc[i][j];
            }
        }
    }
}

// =================== 3b) cand h-part + final combine ===================
struct GateBSmem {
    float sel[64][68];
    float qv[Qq][64];
    float W[2][64][64];
};

__global__ void __launch_bounds__(256, 2) gateB_kernel(
    const float* __restrict__ qv_g, const float* __restrict__ W_c,
    float* __restrict__ out) {
    extern __shared__ char sm_raw[];
    GateBSmem& sm = *reinterpret_cast<GateBSmem*>(sm_raw);
    const int t = threadIdx.x;
    const int k0 = blockIdx.x * 64;

    for (int idx = t; idx < 64 * 64; idx += 256) {
        int r = idx / 64, c = idx % 64;
        sm.sel[c][r] = g_hsel[(k0 + r) * 64 + c];
    }
    for (int idx = t; idx < 64 * Qq; idx += 256) {
        int r = idx / Qq, q = idx % Qq;
        sm.qv[q][r] = qv_g[(k0 + r) * Qq + q];
    }
    for (int idx = t; idx < 64 * 16; idx += 256)
        cp16(&sm.W[0][idx / 16][(idx % 16) * 4],
             &W_c[(65 + idx / 16) * 64 + (idx % 16) * 4]);
    cp_commit();

    const int rg = t >> 4, og = t & 15;
    const int r0 = rg * 4, o0 = og * 4;
    u64t acc2[4][2];
#pragma unroll
    for (int i = 0; i < 4; i++) { acc2[i][0] = 0ull; acc2[i][1] = 0ull; }

    for (int q = 0; q < Qq; q++) {
        const int buf = q & 1;
        if (q + 1 < Qq) {
            for (int idx = t; idx < 64 * 16; idx += 256)
                cp16(&sm.W[buf ^ 1][idx / 16][(idx % 16) * 4],
                     &W_c[((q + 1) * Cc + 65 + idx / 16) * 64 + (idx % 16) * 4]);
        }
        cp_commit();
        cp_wait<1>();
        __syncthreads();

        u64t a2[4][2];
#pragma unroll
        for (int i = 0; i < 4; i++) { a2[i][0] = 0ull; a2[i][1] = 0ull; }
        for (int c = 0; c < 64; c++) {
            float4 a = *(const float4*)&sm.sel[c][r0];
            float4 w = *(const float4*)&sm.W[buf][c][o0];
            u64t wv0, wv1;
            PACK2(wv0, w.x, w.y); PACK2(wv1, w.z, w.w);
            float av[4] = {a.x, a.y, a.z, a.w};
#pragma unroll
            for (int i = 0; i < 4; i++) {
                u64t ad; PACK2(ad, av[i], av[i]);
                FMA2(a2[i][0], ad, wv0, a2[i][0]);
                FMA2(a2[i][1], ad, wv1, a2[i][1]);
            }
        }
        float4 qq = *(const float4*)&sm.qv[q][r0];
        float qvv[4] = {qq.x, qq.y, qq.z, qq.w};
#pragma unroll
        for (int i = 0; i < 4; i++) {
            u64t qd; PACK2(qd, qvv[i], qvv[i]);
            FMA2(acc2[i][0], qd, a2[i][0], acc2[i][0]);
            FMA2(acc2[i][1], qd, a2[i][1], acc2[i][1]);
        }
        __syncthreads();
    }

    float acc[4][4];
#pragma unroll
    for (int i = 0; i < 4; i++) {
        UNPACK2(acc[i][0], acc[i][1], acc2[i][0]);
        UNPACK2(acc[i][2], acc[i][3], acc2[i][1]);
    }
#pragma unroll
    for (int i = 0; i < 4; i++) {
        int kidx = k0 + r0 + i;
#pragma unroll
        for (int j = 0; j < 4; j++) {
            int o = o0 + j;
            float raw = g_cx[kidx * 64 + o] + acc[i][j];
            float cand = tanhf(raw);
            float u  = g_u[kidx * 64 + o];
            float hs = g_hsel[kidx * 64 + o];
            out[kidx * 64 + o] = (1.f - u) * hs + u * cand;
        }
    }
}

// =================== launch ===================
extern "C" void kernel_launch(void* const* d_in, const int* in_sizes, int n_in,
                              void* d_out, int out_size) {
    const float* x   = (const float*)d_in[0];
    const float* h   = (const float*)d_in[1];
    const float* qv  = (const float*)d_in[2];
    const int*   adj = (const int*)d_in[3];
    const int*   nodes = (const int*)d_in[4];
    const float* Wq = (const float*)d_in[5];
    const float* bq = (const float*)d_in[6];
    const float* Wk = (const float*)d_in[7];
    const float* bk = (const float*)d_in[8];
    const float* Wv = (const float*)d_in[9];
    const float* bv = (const float*)d_in[10];
    const float* W_r = (const float*)d_in[11];
    const float* b_r = (const float*)d_in[12];
    const float* W_u = (const float*)d_in[13];
    const float* b_u = (const float*)d_in[14];
    const float* W_c = (const float*)d_in[15];
    const float* b_c = (const float*)d_in[16];
    float* out = (float*)d_out;

    cudaFuncSetAttribute(proj_kernel, cudaFuncAttributeMaxDynamicSharedMemorySize, (int)sizeof(ProjSmem));
    cudaFuncSetAttribute(attn_kernel, cudaFuncAttributeMaxDynamicSharedMemorySize, (int)sizeof(AttnSmem));
    cudaFuncSetAttribute(gateA_kernel, cudaFuncAttributeMaxDynamicSharedMemorySize, (int)sizeof(GateASmem));
    cudaFuncSetAttribute(gateB_kernel, cudaFuncAttributeMaxDynamicSharedMemorySize, (int)sizeof(GateBSmem));

    flag_zero_kernel<<<1, 256>>>();
    flag_mark_kernel<<<Kk / 256, 256>>>(nodes);
    proj_kernel<<<dim3(NROW / 32, 3), 256, sizeof(ProjSmem)>>>(x, h, Wq, bq, Wk, bk, Wv, bv);
    attn_kernel<<<dim3(Nn / RT, Bb), AT, sizeof(AttnSmem)>>>(adj);
    gateA_kernel<<<dim3(Kk / 64, 3), 256, sizeof(GateASmem)>>>(qv, nodes, x, h,
                                                               W_r, b_r, W_u, b_u, W_c, b_c);
    gateB_kernel<<<dim3(Kk / 64, 1), 256, sizeof(GateBSmem)>>>(qv, W_c, out);
}

// round 6
// speedup vs baseline: 1.2924x; 1.2924x over previous
#include <cuda_runtime.h>
#include <math.h>

#define Hh 2
#define Bb 8
#define Nn 2048
#define Dd 64
#define Qq 16
#define Cc 129
#define C8v 16
#define Kk 8192
#define VP 132
#define NEGV (-9.0e15f)
#define NROW (Bb*Nn)
#define RT 64
#define MT 64
#define NTILE (Nn/MT)

// ---------------- packed f32x2 helpers (Blackwell) ----------------
typedef unsigned long long u64t;
#define PACK2(out, lo, hi) \
    asm("mov.b64 %0, {%1, %2};" : "=l"(out) : "f"(lo), "f"(hi))
#define UNPACK2(lo, hi, in) \
    asm("mov.b64 {%0, %1}, %2;" : "=f"(lo), "=f"(hi) : "l"(in))
#define FMA2(d, a, b, c) \
    asm("fma.rn.f32x2 %0, %1, %2, %3;" : "=l"(d) : "l"(a), "l"(b), "l"(c))
#define MUL2(d, a, b) \
    asm("mul.rn.f32x2 %0, %1, %2;" : "=l"(d) : "l"(a), "l"(b))

// ---------------- device scratch ----------------
__device__ float g_q[Hh*NROW*C8v];
__device__ float g_k[Hh*NROW*C8v];
__device__ float g_v[Hh*NROW*VP];
__device__ float g_comb[NROW*VP];
__device__ float g_u[Kk*Dd];
__device__ float g_hsel[Kk*Dd];
__device__ float g_cx[Kk*Dd];
__device__ int   g_batch_flag[Bb];
__device__ int   g_tile_flag[NROW/RT];

// ---------------- cp.async helpers ----------------
__device__ __forceinline__ unsigned smem_u32(const void* p) {
    return (unsigned)__cvta_generic_to_shared(p);
}
__device__ __forceinline__ void cp16(void* dst, const void* src) {
    asm volatile("cp.async.cg.shared.global [%0], [%1], 16;\n"
                 :: "r"(smem_u32(dst)), "l"(src));
}
__device__ __forceinline__ void cp_commit() { asm volatile("cp.async.commit_group;\n"); }
template<int N> __device__ __forceinline__ void cp_wait() {
    asm volatile("cp.async.wait_group %0;\n" :: "n"(N));
}

// ---------------- flags ----------------
__global__ void flag_zero_kernel() {
    int t = threadIdx.x;
    if (t < Bb) g_batch_flag[t] = 0;
    for (int i = t; i < NROW/RT; i += 256) g_tile_flag[i] = 0;
}
__global__ void flag_mark_kernel(const int* __restrict__ nodes) {
    int i = blockIdx.x * 256 + threadIdx.x;
    if (i < Kk) {
        int row = nodes[i];
        g_tile_flag[row >> 6] = 1;
        g_batch_flag[row >> 11] = 1;
    }
}

// =================== 1) QKV projection ===================
struct ProjSmem {
    float comb[Cc][36];
    float W[Cc][VP];
    float bias[VP];
};

__global__ void proj_kernel(const float* __restrict__ x, const float* __restrict__ h,
                            const float* __restrict__ Wq, const float* __restrict__ bq,
                            const float* __restrict__ Wk, const float* __restrict__ bk,
                            const float* __restrict__ Wv, const float* __restrict__ bv) {
    extern __shared__ char sm_raw[];
    ProjSmem& sm = *reinterpret_cast<ProjSmem*>(sm_raw);
    const int t = threadIdx.x;
    const int row0 = blockIdx.x * 32;
    if (!g_batch_flag[row0 >> 11]) return;
    const int y = blockIdx.y;

    for (int idx = t; idx < 32 * Cc; idx += 256) {
        int r = idx / Cc, c = idx % Cc;
        int row = row0 + r;
        float v = (c < 65) ? x[row * 65 + c] : h[row * 64 + (c - 65)];
        sm.comb[c][r] = v;
    }
    if (y == 0) {
        for (int idx = t; idx < Cc * 64; idx += 256) {
            int c = idx / 64, o = idx % 64;
            float w;
            if (o < 32)      w = Wq[((o >> 4) * Cc + c) * C8v + (o & 15)];
            else { int o2 = o - 32; w = Wk[((o2 >> 4) * Cc + c) * C8v + (o2 & 15)]; }
            sm.W[c][o] = w;
        }
        if (t < 64) {
            float b;
            if (t < 32)      b = bq[(t >> 4) * C8v + (t & 15)];
            else { int o2 = t - 32; b = bk[(o2 >> 4) * C8v + (o2 & 15)]; }
            sm.bias[t] = b;
        }
    } else {
        int hh = y - 1;
        for (int idx = t; idx < Cc * VP; idx += 256) {
            int c = idx / VP, o = idx % VP;
            sm.W[c][o] = (o < Cc) ? Wv[(hh * Cc + c) * Cc + o] : 0.f;
        }
        for (int o = t; o < VP; o += 256) sm.bias[o] = (o < Cc) ? bv[hh * Cc + o] : 0.f;
    }
    __syncthreads();

    if (y == 0) {
        int r = t >> 3, og = t & 7;
        int c0 = og * 8;
        float acc[8];
#pragma unroll
        for (int j = 0; j < 8; j++) acc[j] = 0.f;
        for (int c = 0; c < Cc; c++) {
            float a = sm.comb[c][r];
#pragma unroll
            for (int j = 0; j < 8; j++) acc[j] += a * sm.W[c][c0 + j];
        }
        int row = row0 + r;
#pragma unroll
        for (int j = 0; j < 8; j++) {
            int o = c0 + j;
            float val = acc[j] + sm.bias[o];
            if (o < 32) {
                g_q[(((o >> 4) * NROW) + row) * C8v + (o & 15)] = val;
            } else {
                int o2 = o - 32;
                g_k[(((o2 >> 4) * NROW) + row) * C8v + (o2 & 15)] = val;
            }
        }
    } else {
        int hh = y - 1;
        int r = t >> 3, og = t & 7;
        int c0 = og * 16;
        int xcol = 128 + og;
        float acc[17];
#pragma unroll
        for (int j = 0; j < 17; j++) acc[j] = 0.f;
        for (int c = 0; c < Cc; c++) {
            float a = sm.comb[c][r];
#pragma unroll
            for (int j = 0; j < 16; j++) acc[j] += a * sm.W[c][c0 + j];
            if (og < 4) acc[16] += a * sm.W[c][xcol];
        }
        int row = row0 + r;
        float* dst = &g_v[((hh * NROW) + row) * VP];
#pragma unroll
        for (int j = 0; j < 16; j++) dst[c0 + j] = acc[j] + sm.bias[c0 + j];
        if (og < 4) dst[xcol] = acc[16] + sm.bias[xcol];
    }
}

// =================== 2) attention (256 thr, MT=64, fused score+softmax) ===================
struct AttnSmem {
    float v[2][Hh][MT][VP];      // 135168 B
    float k[2][Hh][MT][C8v];     //  16384 B
    int   adj[2][RT][68];        //  34816 B
    float p[Hh][MT][RT];         //  32768 B
    float rmax[Hh][RT];
    float rsum[Hh][RT];
    float fac[Hh][RT];
};                               // ~215 KB

__device__ __forceinline__ void attn_prefetch(AttnSmem& sm, int buf, int b, int row0,
                                              int m0, const int* __restrict__ adjg, int t) {
    for (int idx = t; idx < Hh * MT * 33; idx += 256) {
        int h_ = idx / (MT * 33), rem = idx % (MT * 33), m = rem / 33, c4 = rem % 33;
        cp16(&sm.v[buf][h_][m][c4 * 4],
             &g_v[((h_ * NROW) + b * Nn + m0 + m) * VP + c4 * 4]);
    }
    for (int idx = t; idx < Hh * MT * 4; idx += 256) {
        int h_ = idx / (MT * 4), rem = idx % (MT * 4), m = rem >> 2, d4 = rem & 3;
        cp16(&sm.k[buf][h_][m][d4 * 4],
             &g_k[((h_ * NROW) + b * Nn + m0 + m) * C8v + d4 * 4]);
    }
    for (int idx = t; idx < RT * 16; idx += 256) {
        int r = idx >> 4, c4 = idx & 15;
        cp16(&sm.adj[buf][r][c4 * 4],
             &adjg[(b * Nn + row0 + r) * Nn + m0 + c4 * 4]);
    }
}

__global__ void __launch_bounds__(256, 1) attn_kernel(const int* __restrict__ adjg) {
    extern __shared__ char sm_raw[];
    AttnSmem& sm = *reinterpret_cast<AttnSmem*>(sm_raw);
    const int t = threadIdx.x;
    const int b = blockIdx.y;
    const int row0 = blockIdx.x * RT;
    if (!g_tile_flag[(b * Nn + row0) >> 6]) return;

    const int s_hh = t >> 7, s_r = (t & 127) >> 1, s_half = t & 1;
    const int p_hh = t >> 7;
    const int t7 = t & 127;
    const int r0 = (t7 >> 4) * 8, c0 = (t7 & 15) * 8;
    const int x_hh = t >> 6, x_r = t & 63;

    float qreg[16];
    {
        const float4* qsrc = (const float4*)&g_q[((s_hh * NROW) + b * Nn + row0 + s_r) * C8v];
#pragma unroll
        for (int j = 0; j < 4; j++) {
            float4 qq = qsrc[j];
            qreg[4 * j] = qq.x; qreg[4 * j + 1] = qq.y;
            qreg[4 * j + 2] = qq.z; qreg[4 * j + 3] = qq.w;
        }
    }
    // per-thread row state (the pair shares it via shfl, owner = s_half==0... both keep copies)
    float rmax_t = -INFINITY, rsum_t = 0.f;

    u64t acc2[8][4];
#pragma unroll
    for (int i = 0; i < 8; i++)
#pragma unroll
        for (int j = 0; j < 4; j++) acc2[i][j] = 0ull;
    float acc128 = 0.f;

    attn_prefetch(sm, 0, b, row0, 0, adjg, t);
    cp_commit();

    for (int mt = 0; mt < NTILE; mt++) {
        const int buf = mt & 1;
        if (mt + 1 < NTILE) attn_prefetch(sm, buf ^ 1, b, row0, (mt + 1) * MT, adjg, t);
        cp_commit();
        cp_wait<1>();
        __syncthreads();

        // ---- fused scores + online softmax (in registers) ----
        {
            float e[32];
            float tmax = -INFINITY;
#pragma unroll 4
            for (int i = 0; i < 32; i++) {
                int m = s_half * 32 + i;
                const float4* k4 = (const float4*)&sm.k[buf][s_hh][m][0];
                float s = 0.f;
#pragma unroll
                for (int d4 = 0; d4 < 4; d4++) {
                    float4 kk = k4[d4];
                    s += qreg[4 * d4] * kk.x + qreg[4 * d4 + 1] * kk.y
                       + qreg[4 * d4 + 2] * kk.z + qreg[4 * d4 + 3] * kk.w;
                }
                s *= 0.25f;
                s = (s > 0.f) ? s : 0.2f * s;
                if (sm.adj[buf][s_r][m] == 0) s = NEGV;
                e[i] = s;
                tmax = fmaxf(tmax, s);
            }
            tmax = fmaxf(tmax, __shfl_xor_sync(0xffffffffu, tmax, 1));
            float nmax = fmaxf(rmax_t, tmax);
            float ssum = 0.f;
#pragma unroll 4
            for (int i = 0; i < 32; i++) {
                float ex = __expf(e[i] - nmax);
                sm.p[s_hh][s_half * 32 + i][s_r] = ex;
                ssum += ex;
            }
            ssum += __shfl_xor_sync(0xffffffffu, ssum, 1);
            float f = __expf(rmax_t - nmax);
            rsum_t = rsum_t * f + ssum;
            rmax_t = nmax;
            if (s_half == 0) sm.fac[s_hh][s_r] = f;
        }
        __syncthreads();

        // ---- PV accumulate (packed f32x2, 8 rows x 8 cols) ----
        {
#pragma unroll
            for (int i = 0; i < 8; i++) {
                float f = sm.fac[p_hh][r0 + i];
                u64t fd; PACK2(fd, f, f);
#pragma unroll
                for (int j = 0; j < 4; j++) MUL2(acc2[i][j], acc2[i][j], fd);
            }
            if (t < 128) acc128 *= sm.fac[x_hh][x_r];

#pragma unroll 2
            for (int m = 0; m < MT; m++) {
                float4 p0 = *(const float4*)&sm.p[p_hh][m][r0];
                float4 p1 = *(const float4*)&sm.p[p_hh][m][r0 + 4];
                float4 v0 = *(const float4*)&sm.v[buf][p_hh][m][c0];
                float4 v1 = *(const float4*)&sm.v[buf][p_hh][m][c0 + 4];
                u64t vv[4];
                PACK2(vv[0], v0.x, v0.y); PACK2(vv[1], v0.z, v0.w);
                PACK2(vv[2], v1.x, v1.y); PACK2(vv[3], v1.z, v1.w);
                float pv[8] = {p0.x, p0.y, p0.z, p0.w, p1.x, p1.y, p1.z, p1.w};
#pragma unroll
                for (int i = 0; i < 8; i++) {
                    u64t pd; PACK2(pd, pv[i], pv[i]);
#pragma unroll
                    for (int j = 0; j < 4; j++)
                        FMA2(acc2[i][j], pd, vv[j], acc2[i][j]);
                }
            }
            if (t < 128) {
#pragma unroll 4
                for (int m = 0; m < MT; m++)
                    acc128 += sm.p[x_hh][m][x_r] * sm.v[buf][x_hh][m][128];
            }
        }
        __syncthreads();
    }

    // publish row sums (score threads own them)
    if (s_half == 0) sm.rsum[s_hh][s_r] = rsum_t;
    __syncthreads();

    // ---- finalize: mean over heads ----
    float accf[8][8];
#pragma unroll
    for (int i = 0; i < 8; i++) {
        float inv = 0.5f / sm.rsum[p_hh][r0 + i];
#pragma unroll
        for (int j = 0; j < 4; j++) {
            float lo, hi;
            UNPACK2(lo, hi, acc2[i][j]);
            accf[i][2 * j] = lo * inv;
            accf[i][2 * j + 1] = hi * inv;
        }
    }

    float* osh = (float*)&sm.v[0][0][0][0];
    if (p_hh == 0) {
#pragma unroll
        for (int i = 0; i < 8; i++)
#pragma unroll
            for (int j = 0; j < 8; j++)
                osh[(r0 + i) * VP + (c0 + j)] = accf[i][j];
    }
    if (t < 64) osh[x_r * VP + 128] = acc128 * (0.5f / sm.rsum[0][x_r]);
    __syncthreads();
    if (p_hh == 1) {
#pragma unroll
        for (int i = 0; i < 8; i++)
#pragma unroll
            for (int j = 0; j < 8; j++)
                osh[(r0 + i) * VP + (c0 + j)] += accf[i][j];
    }
    if (t >= 64 && t < 128) osh[x_r * VP + 128] += acc128 * (0.5f / sm.rsum[1][x_r]);
    __syncthreads();

    for (int idx = t; idx < RT * Cc; idx += 256) {
        int r = idx / Cc, c = idx % Cc;
        g_comb[(b * Nn + row0 + r) * VP + c] = osh[r * VP + c];
    }
}

// =================== 3a) gates r, u, cand_x ===================
struct GateASmem {
    float sel[Cc][68];
    float qv[Qq][64];
    float W[2][Cc][64];
    int   nodes[64];
};

__global__ void __launch_bounds__(256, 2) gateA_kernel(
    const float* __restrict__ qv_g, const int* __restrict__ nodes,
    const float* __restrict__ x_g, const float* __restrict__ h_g,
    const float* __restrict__ W_r, const float* __restrict__ b_r,
    const float* __restrict__ W_u, const float* __restrict__ b_u,
    const float* __restrict__ W_c, const float* __restrict__ b_c) {
    extern __shared__ char sm_raw[];
    GateASmem& sm = *reinterpret_cast<GateASmem*>(sm_raw);
    const int t = threadIdx.x;
    const int k0 = blockIdx.x * 64;
    const int g = blockIdx.y;
    const float* W    = (g == 0) ? W_r : (g == 1) ? W_u : W_c;
    const float* bias = (g == 0) ? b_r : (g == 1) ? b_u : b_c;
    const int CN = (g == 2) ? 65 : Cc;
    const int NCH = CN * 16;

    if (t < 64) sm.nodes[t] = nodes[k0 + t];
    __syncthreads();
    if (g == 2) {
        for (int idx = t; idx < 64 * 65; idx += 256) {
            int r = idx / 65, c = idx % 65;
            sm.sel[c][r] = x_g[sm.nodes[r] * 65 + c];
        }
    } else {
        for (int idx = t; idx < 64 * Cc; idx += 256) {
            int r = idx / Cc, c = idx % Cc;
            sm.sel[c][r] = g_comb[sm.nodes[r] * VP + c];
        }
    }
    for (int idx = t; idx < 64 * Qq; idx += 256) {
        int r = idx / Qq, q = idx % Qq;
        sm.qv[q][r] = qv_g[(k0 + r) * Qq + q];
    }
    for (int idx = t; idx < NCH; idx += 256)
        cp16(&sm.W[0][idx / 16][(idx % 16) * 4], &W[(idx / 16) * 64 + (idx % 16) * 4]);
    cp_commit();

    const int rg = t >> 4, og = t & 15;
    const int r0 = rg * 4, o0 = og * 4;
    u64t acc2[4][2];
#pragma unroll
    for (int i = 0; i < 4; i++) { acc2[i][0] = 0ull; acc2[i][1] = 0ull; }

    for (int q = 0; q < Qq; q++) {
        const int buf = q & 1;
        if (q + 1 < Qq) {
            for (int idx = t; idx < NCH; idx += 256)
                cp16(&sm.W[buf ^ 1][idx / 16][(idx % 16) * 4],
                     &W[((q + 1) * Cc + idx / 16) * 64 + (idx % 16) * 4]);
        }
        cp_commit();
        cp_wait<1>();
        __syncthreads();

        u64t a2[4][2];
#pragma unroll
        for (int i = 0; i < 4; i++) { a2[i][0] = 0ull; a2[i][1] = 0ull; }
        for (int c = 0; c < CN; c++) {
            float4 a = *(const float4*)&sm.sel[c][r0];
            float4 w = *(const float4*)&sm.W[buf][c][o0];
            u64t wv0, wv1;
            PACK2(wv0, w.x, w.y); PACK2(wv1, w.z, w.w);
            float av[4] = {a.x, a.y, a.z, a.w};
#pragma unroll
            for (int i = 0; i < 4; i++) {
                u64t ad; PACK2(ad, av[i], av[i]);
                FMA2(a2[i][0], ad, wv0, a2[i][0]);
                FMA2(a2[i][1], ad, wv1, a2[i][1]);
            }
        }
        float4 qq = *(const float4*)&sm.qv[q][r0];
        float qvv[4] = {qq.x, qq.y, qq.z, qq.w};
#pragma unroll
        for (int i = 0; i < 4; i++) {
            u64t qd; PACK2(qd, qvv[i], qvv[i]);
            FMA2(acc2[i][0], qd, a2[i][0], acc2[i][0]);
            FMA2(acc2[i][1], qd, a2[i][1], acc2[i][1]);
        }
        __syncthreads();
    }

    float acc[4][4];
#pragma unroll
    for (int i = 0; i < 4; i++) {
        UNPACK2(acc[i][0], acc[i][1], acc2[i][0]);
        UNPACK2(acc[i][2], acc[i][3], acc2[i][1]);
    }
    for (int q = 0; q < Qq; q++) {
        float4 bb = *(const float4*)&bias[q * 64 + o0];
        float bv4[4] = {bb.x, bb.y, bb.z, bb.w};
        float4 qq = *(const float4*)&sm.qv[q][r0];
        float qvv[4] = {qq.x, qq.y, qq.z, qq.w};
#pragma unroll
        for (int i = 0; i < 4; i++)
#pragma unroll
            for (int j = 0; j < 4; j++) acc[i][j] += qvv[i] * bv4[j];
    }
#pragma unroll
    for (int i = 0; i < 4; i++) {
        int kidx = k0 + r0 + i;
#pragma unroll
        for (int j = 0; j < 4; j++) {
            int o = o0 + j;
            if (g == 0) {
                float z = 1.f / (1.f + __expf(-acc[i][j]));
                g_hsel[kidx * 64 + o] = z * h_g[sm.nodes[r0 + i] * 64 + o];
            } else if (g == 1) {
                g_u[kidx * 64 + o] = 1.f / (1.f + __expf(-acc[i][j]));
            } else {
                g_cx[kidx * 64 + o] = acc[i][j];
            }
        }
    }
}

// =================== 3b) cand h-part + final combine ===================
struct GateBSmem {
    float sel[64][68];
    float qv[Qq][64];
    float W[2][64][64];
};

__global__ void __launch_bounds__(256, 2) gateB_kernel(
    const float* __restrict__ qv_g, const float* __restrict__ W_c,
    float* __restrict__ out) {
    extern __shared__ char sm_raw[];
    GateBSmem& sm = *reinterpret_cast<GateBSmem*>(sm_raw);
    const int t = threadIdx.x;
    const int k0 = blockIdx.x * 64;

    for (int idx = t; idx < 64 * 64; idx += 256) {
        int r = idx / 64, c = idx % 64;
        sm.sel[c][r] = g_hsel[(k0 + r) * 64 + c];
    }
    for (int idx = t; idx < 64 * Qq; idx += 256) {
        int r = idx / Qq, q = idx % Qq;
        sm.qv[q][r] = qv_g[(k0 + r) * Qq + q];
    }
    for (int idx = t; idx < 64 * 16; idx += 256)
        cp16(&sm.W[0][idx / 16][(idx % 16) * 4],
             &W_c[(65 + idx / 16) * 64 + (idx % 16) * 4]);
    cp_commit();

    const int rg = t >> 4, og = t & 15;
    const int r0 = rg * 4, o0 = og * 4;
    u64t acc2[4][2];
#pragma unroll
    for (int i = 0; i < 4; i++) { acc2[i][0] = 0ull; acc2[i][1] = 0ull; }

    for (int q = 0; q < Qq; q++) {
        const int buf = q & 1;
        if (q + 1 < Qq) {
            for (int idx = t; idx < 64 * 16; idx += 256)
                cp16(&sm.W[buf ^ 1][idx / 16][(idx % 16) * 4],
                     &W_c[((q + 1) * Cc + 65 + idx / 16) * 64 + (idx % 16) * 4]);
        }
        cp_commit();
        cp_wait<1>();
        __syncthreads();

        u64t a2[4][2];
#pragma unroll
        for (int i = 0; i < 4; i++) { a2[i][0] = 0ull; a2[i][1] = 0ull; }
        for (int c = 0; c < 64; c++) {
            float4 a = *(const float4*)&sm.sel[c][r0];
            float4 w = *(const float4*)&sm.W[buf][c][o0];
            u64t wv0, wv1;
            PACK2(wv0, w.x, w.y); PACK2(wv1, w.z, w.w);
            float av[4] = {a.x, a.y, a.z, a.w};
#pragma unroll
            for (int i = 0; i < 4; i++) {
                u64t ad; PACK2(ad, av[i], av[i]);
                FMA2(a2[i][0], ad, wv0, a2[i][0]);
                FMA2(a2[i][1], ad, wv1, a2[i][1]);
            }
        }
        float4 qq = *(const float4*)&sm.qv[q][r0];
        float qvv[4] = {qq.x, qq.y, qq.z, qq.w};
#pragma unroll
        for (int i = 0; i < 4; i++) {
            u64t qd; PACK2(qd, qvv[i], qvv[i]);
            FMA2(acc2[i][0], qd, a2[i][0], acc2[i][0]);
            FMA2(acc2[i][1], qd, a2[i][1], acc2[i][1]);
        }
        __syncthreads();
    }

    float acc[4][4];
#pragma unroll
    for (int i = 0; i < 4; i++) {
        UNPACK2(acc[i][0], acc[i][1], acc2[i][0]);
        UNPACK2(acc[i][2], acc[i][3], acc2[i][1]);
    }
#pragma unroll
    for (int i = 0; i < 4; i++) {
        int kidx = k0 + r0 + i;
#pragma unroll
        for (int j = 0; j < 4; j++) {
            int o = o0 + j;
            float raw = g_cx[kidx * 64 + o] + acc[i][j];
            float cand = tanhf(raw);
            float u  = g_u[kidx * 64 + o];
            float hs = g_hsel[kidx * 64 + o];
            out[kidx * 64 + o] = (1.f - u) * hs + u * cand;
        }
    }
}

// =================== launch ===================
extern "C" void kernel_launch(void* const* d_in, const int* in_sizes, int n_in,
                              void* d_out, int out_size) {
    const float* x   = (const float*)d_in[0];
    const float* h   = (const float*)d_in[1];
    const float* qv  = (const float*)d_in[2];
    const int*   adj = (const int*)d_in[3];
    const int*   nodes = (const int*)d_in[4];
    const float* Wq = (const float*)d_in[5];
    const float* bq = (const float*)d_in[6];
    const float* Wk = (const float*)d_in[7];
    const float* bk = (const float*)d_in[8];
    const float* Wv = (const float*)d_in[9];
    const float* bv = (const float*)d_in[10];
    const float* W_r = (const float*)d_in[11];
    const float* b_r = (const float*)d_in[12];
    const float* W_u = (const float*)d_in[13];
    const float* b_u = (const float*)d_in[14];
    const float* W_c = (const float*)d_in[15];
    const float* b_c = (const float*)d_in[16];
    float* out = (float*)d_out;

    cudaFuncSetAttribute(proj_kernel, cudaFuncAttributeMaxDynamicSharedMemorySize, (int)sizeof(ProjSmem));
    cudaFuncSetAttribute(attn_kernel, cudaFuncAttributeMaxDynamicSharedMemorySize, (int)sizeof(AttnSmem));
    cudaFuncSetAttribute(gateA_kernel, cudaFuncAttributeMaxDynamicSharedMemorySize, (int)sizeof(GateASmem));
    cudaFuncSetAttribute(gateB_kernel, cudaFuncAttributeMaxDynamicSharedMemorySize, (int)sizeof(GateBSmem));

    flag_zero_kernel<<<1, 256>>>();
    flag_mark_kernel<<<Kk / 256, 256>>>(nodes);
    proj_kernel<<<dim3(NROW / 32, 3), 256, sizeof(ProjSmem)>>>(x, h, Wq, bq, Wk, bk, Wv, bv);
    attn_kernel<<<dim3(Nn / RT, Bb), 256, sizeof(AttnSmem)>>>(adj);
    gateA_kernel<<<dim3(Kk / 64, 3), 256, sizeof(GateASmem)>>>(qv, nodes, x, h,
                                                               W_r, b_r, W_u, b_u, W_c, b_c);
    gateB_kernel<<<dim3(Kk / 64, 1), 256, sizeof(GateBSmem)>>>(qv, W_c, out);
}

// round 7
// speedup vs baseline: 1.3370x; 1.0345x over previous
#include <cuda_runtime.h>
#include <math.h>

#define Hh 2
#define Bb 8
#define Nn 2048
#define Dd 64
#define Qq 16
#define Cc 129
#define C8v 16
#define Kk 8192
#define VP 132
#define NEGV (-9.0e15f)
#define NROW (Bb*Nn)
#define RT 64
#define MT 64
#define NTILE (Nn/MT)

// ---------------- packed f32x2 helpers (Blackwell) ----------------
typedef unsigned long long u64t;
#define PACK2(out, lo, hi) \
    asm("mov.b64 %0, {%1, %2};" : "=l"(out) : "f"(lo), "f"(hi))
#define UNPACK2(lo, hi, in) \
    asm("mov.b64 {%0, %1}, %2;" : "=f"(lo), "=f"(hi) : "l"(in))
#define FMA2(d, a, b, c) \
    asm("fma.rn.f32x2 %0, %1, %2, %3;" : "=l"(d) : "l"(a), "l"(b), "l"(c))
#define MUL2(d, a, b) \
    asm("mul.rn.f32x2 %0, %1, %2;" : "=l"(d) : "l"(a), "l"(b))

// ---------------- device scratch ----------------
__device__ float g_q[Hh*NROW*C8v];
__device__ float g_k[Hh*NROW*C8v];
__device__ float g_v[Hh*NROW*VP];
__device__ float g_comb[NROW*VP];
__device__ float g_u[Kk*Dd];
__device__ float g_hsel[Kk*Dd];
__device__ float g_cx[Kk*Dd];
__device__ int   g_batch_flag[Bb];
__device__ int   g_tile_flag[NROW/RT];

// ---------------- cp.async helpers ----------------
__device__ __forceinline__ unsigned smem_u32(const void* p) {
    return (unsigned)__cvta_generic_to_shared(p);
}
__device__ __forceinline__ void cp16(void* dst, const void* src) {
    asm volatile("cp.async.cg.shared.global [%0], [%1], 16;\n"
                 :: "r"(smem_u32(dst)), "l"(src));
}
__device__ __forceinline__ void cp_commit() { asm volatile("cp.async.commit_group;\n"); }
template<int N> __device__ __forceinline__ void cp_wait() {
    asm volatile("cp.async.wait_group %0;\n" :: "n"(N));
}

// ---------------- flags ----------------
__global__ void flag_zero_kernel() {
    int t = threadIdx.x;
    if (t < Bb) g_batch_flag[t] = 0;
    for (int i = t; i < NROW/RT; i += 256) g_tile_flag[i] = 0;
}
__global__ void flag_mark_kernel(const int* __restrict__ nodes) {
    int i = blockIdx.x * 256 + threadIdx.x;
    if (i < Kk) {
        int row = nodes[i];
        g_tile_flag[row >> 6] = 1;
        g_batch_flag[row >> 11] = 1;
    }
}

// =================== 1) QKV projection ===================
struct ProjSmem {
    float comb[Cc][36];
    float W[Cc][VP];
    float bias[VP];
};

__global__ void proj_kernel(const float* __restrict__ x, const float* __restrict__ h,
                            const float* __restrict__ Wq, const float* __restrict__ bq,
                            const float* __restrict__ Wk, const float* __restrict__ bk,
                            const float* __restrict__ Wv, const float* __restrict__ bv) {
    extern __shared__ char sm_raw[];
    ProjSmem& sm = *reinterpret_cast<ProjSmem*>(sm_raw);
    const int t = threadIdx.x;
    const int row0 = blockIdx.x * 32;
    if (!g_batch_flag[row0 >> 11]) return;
    const int y = blockIdx.y;

    for (int idx = t; idx < 32 * Cc; idx += 256) {
        int r = idx / Cc, c = idx % Cc;
        int row = row0 + r;
        float v = (c < 65) ? x[row * 65 + c] : h[row * 64 + (c - 65)];
        sm.comb[c][r] = v;
    }
    if (y == 0) {
        for (int idx = t; idx < Cc * 64; idx += 256) {
            int c = idx / 64, o = idx % 64;
            float w;
            if (o < 32)      w = Wq[((o >> 4) * Cc + c) * C8v + (o & 15)];
            else { int o2 = o - 32; w = Wk[((o2 >> 4) * Cc + c) * C8v + (o2 & 15)]; }
            sm.W[c][o] = w;
        }
        if (t < 64) {
            float b;
            if (t < 32)      b = bq[(t >> 4) * C8v + (t & 15)];
            else { int o2 = t - 32; b = bk[(o2 >> 4) * C8v + (o2 & 15)]; }
            sm.bias[t] = b;
        }
    } else {
        int hh = y - 1;
        for (int idx = t; idx < Cc * VP; idx += 256) {
            int c = idx / VP, o = idx % VP;
            sm.W[c][o] = (o < Cc) ? Wv[(hh * Cc + c) * Cc + o] : 0.f;
        }
        for (int o = t; o < VP; o += 256) sm.bias[o] = (o < Cc) ? bv[hh * Cc + o] : 0.f;
    }
    __syncthreads();

    if (y == 0) {
        int r = t >> 3, og = t & 7;
        int c0 = og * 8;
        float acc[8];
#pragma unroll
        for (int j = 0; j < 8; j++) acc[j] = 0.f;
        for (int c = 0; c < Cc; c++) {
            float a = sm.comb[c][r];
#pragma unroll
            for (int j = 0; j < 8; j++) acc[j] += a * sm.W[c][c0 + j];
        }
        int row = row0 + r;
#pragma unroll
        for (int j = 0; j < 8; j++) {
            int o = c0 + j;
            float val = acc[j] + sm.bias[o];
            if (o < 32) {
                g_q[(((o >> 4) * NROW) + row) * C8v + (o & 15)] = val;
            } else {
                int o2 = o - 32;
                g_k[(((o2 >> 4) * NROW) + row) * C8v + (o2 & 15)] = val;
            }
        }
    } else {
        int hh = y - 1;
        int r = t >> 3, og = t & 7;
        int c0 = og * 16;
        int xcol = 128 + og;
        float acc[17];
#pragma unroll
        for (int j = 0; j < 17; j++) acc[j] = 0.f;
        for (int c = 0; c < Cc; c++) {
            float a = sm.comb[c][r];
#pragma unroll
            for (int j = 0; j < 16; j++) acc[j] += a * sm.W[c][c0 + j];
            if (og < 4) acc[16] += a * sm.W[c][xcol];
        }
        int row = row0 + r;
        float* dst = &g_v[((hh * NROW) + row) * VP];
#pragma unroll
        for (int j = 0; j < 16; j++) dst[c0 + j] = acc[j] + sm.bias[c0 + j];
        if (og < 4) dst[xcol] = acc[16] + sm.bias[xcol];
    }
}

// =================== 2) attention (round-2 config: 256 thr, MT=64, FMA2 PV) ===================
struct AttnSmem {
    float v[2][Hh][MT][VP];
    float k[2][Hh][MT][C8v];
    int   adj[2][RT][68];
    float p[Hh][MT][RT];
    float rmax[Hh][RT];
    float rsum[Hh][RT];
    float fac[Hh][RT];
};

__device__ __forceinline__ void attn_prefetch(AttnSmem& sm, int buf, int b, int row0,
                                              int m0, const int* __restrict__ adjg, int t) {
    for (int idx = t; idx < Hh * MT * 33; idx += 256) {
        int h_ = idx / (MT * 33), rem = idx % (MT * 33), m = rem / 33, c4 = rem % 33;
        cp16(&sm.v[buf][h_][m][c4 * 4],
             &g_v[((h_ * NROW) + b * Nn + m0 + m) * VP + c4 * 4]);
    }
    for (int idx = t; idx < Hh * MT * 4; idx += 256) {
        int h_ = idx / (MT * 4), rem = idx % (MT * 4), m = rem >> 2, d4 = rem & 3;
        cp16(&sm.k[buf][h_][m][d4 * 4],
             &g_k[((h_ * NROW) + b * Nn + m0 + m) * C8v + d4 * 4]);
    }
    for (int idx = t; idx < RT * 16; idx += 256) {
        int r = idx >> 4, c4 = idx & 15;
        cp16(&sm.adj[buf][r][c4 * 4],
             &adjg[(b * Nn + row0 + r) * Nn + m0 + c4 * 4]);
    }
}

__global__ void __launch_bounds__(256, 1) attn_kernel(const int* __restrict__ adjg) {
    extern __shared__ char sm_raw[];
    AttnSmem& sm = *reinterpret_cast<AttnSmem*>(sm_raw);
    const int t = threadIdx.x;
    const int b = blockIdx.y;
    const int row0 = blockIdx.x * RT;
    if (!g_tile_flag[(b * Nn + row0) >> 6]) return;

    const int s_hh = t >> 7, s_r = (t & 127) >> 1, s_half = t & 1;
    const int p_hh = t >> 7;
    const int t7 = t & 127;
    const int r0 = (t7 >> 4) * 8, c0 = (t7 & 15) * 8;
    const int x_hh = t >> 6, x_r = t & 63;

    float qreg[16];
    {
        const float4* qsrc = (const float4*)&g_q[((s_hh * NROW) + b * Nn + row0 + s_r) * C8v];
#pragma unroll
        for (int j = 0; j < 4; j++) {
            float4 qq = qsrc[j];
            qreg[4 * j] = qq.x; qreg[4 * j + 1] = qq.y;
            qreg[4 * j + 2] = qq.z; qreg[4 * j + 3] = qq.w;
        }
    }
    if (t < 128) { sm.rmax[x_hh][x_r] = -INFINITY; sm.rsum[x_hh][x_r] = 0.f; }

    u64t acc2[8][4];
#pragma unroll
    for (int i = 0; i < 8; i++)
#pragma unroll
        for (int j = 0; j < 4; j++) acc2[i][j] = 0ull;
    float acc128 = 0.f;

    attn_prefetch(sm, 0, b, row0, 0, adjg, t);
    cp_commit();

    for (int mt = 0; mt < NTILE; mt++) {
        const int buf = mt & 1;
        if (mt + 1 < NTILE) attn_prefetch(sm, buf ^ 1, b, row0, (mt + 1) * MT, adjg, t);
        cp_commit();
        cp_wait<1>();
        __syncthreads();

        // ---- scores ----
        {
#pragma unroll 4
            for (int i = 0; i < 32; i++) {
                int m = s_half * 32 + i;
                const float4* k4 = (const float4*)&sm.k[buf][s_hh][m][0];
                float s = 0.f;
#pragma unroll
                for (int d4 = 0; d4 < 4; d4++) {
                    float4 kk = k4[d4];
                    s += qreg[4 * d4] * kk.x + qreg[4 * d4 + 1] * kk.y
                       + qreg[4 * d4 + 2] * kk.z + qreg[4 * d4 + 3] * kk.w;
                }
                s *= 0.25f;
                s = (s > 0.f) ? s : 0.2f * s;
                if (sm.adj[buf][s_r][m] == 0) s = NEGV;
                sm.p[s_hh][m][s_r] = s;
            }
        }
        __syncthreads();

        // ---- online softmax (pair of threads per row) ----
        {
            int pr = t >> 1;
            int ph = pr >> 6, rr = pr & 63, hf = t & 1;
            float tmax = -INFINITY;
#pragma unroll 4
            for (int j = 0; j < 32; j++)
                tmax = fmaxf(tmax, sm.p[ph][hf * 32 + j][rr]);
            tmax = fmaxf(tmax, __shfl_xor_sync(0xffffffffu, tmax, 1));
            float oldmax = sm.rmax[ph][rr];
            float nmax = fmaxf(oldmax, tmax);
            float ssum = 0.f;
#pragma unroll 4
            for (int j = 0; j < 32; j++) {
                int m = hf * 32 + j;
                float e = __expf(sm.p[ph][m][rr] - nmax);
                sm.p[ph][m][rr] = e;
                ssum += e;
            }
            ssum += __shfl_xor_sync(0xffffffffu, ssum, 1);
            if (hf == 0) {
                float f = __expf(oldmax - nmax);
                sm.fac[ph][rr] = f;
                sm.rsum[ph][rr] = sm.rsum[ph][rr] * f + ssum;
                sm.rmax[ph][rr] = nmax;
            }
        }
        __syncthreads();

        // ---- PV accumulate (packed f32x2) ----
        {
#pragma unroll
            for (int i = 0; i < 8; i++) {
                float f = sm.fac[p_hh][r0 + i];
                u64t fd; PACK2(fd, f, f);
#pragma unroll
                for (int j = 0; j < 4; j++) MUL2(acc2[i][j], acc2[i][j], fd);
            }
            if (t < 128) acc128 *= sm.fac[x_hh][x_r];

#pragma unroll 2
            for (int m = 0; m < MT; m++) {
                float4 p0 = *(const float4*)&sm.p[p_hh][m][r0];
                float4 p1 = *(const float4*)&sm.p[p_hh][m][r0 + 4];
                float4 v0 = *(const float4*)&sm.v[buf][p_hh][m][c0];
                float4 v1 = *(const float4*)&sm.v[buf][p_hh][m][c0 + 4];
                u64t vv[4];
                PACK2(vv[0], v0.x, v0.y); PACK2(vv[1], v0.z, v0.w);
                PACK2(vv[2], v1.x, v1.y); PACK2(vv[3], v1.z, v1.w);
                float pv[8] = {p0.x, p0.y, p0.z, p0.w, p1.x, p1.y, p1.z, p1.w};
#pragma unroll
                for (int i = 0; i < 8; i++) {
                    u64t pd; PACK2(pd, pv[i], pv[i]);
#pragma unroll
                    for (int j = 0; j < 4; j++)
                        FMA2(acc2[i][j], pd, vv[j], acc2[i][j]);
                }
            }
            if (t < 128) {
#pragma unroll 4
                for (int m = 0; m < MT; m++)
                    acc128 += sm.p[x_hh][m][x_r] * sm.v[buf][x_hh][m][128];
            }
        }
        __syncthreads();
    }

    // ---- finalize: mean over heads ----
    float accf[8][8];
#pragma unroll
    for (int i = 0; i < 8; i++) {
        float inv = 0.5f / sm.rsum[p_hh][r0 + i];
#pragma unroll
        for (int j = 0; j < 4; j++) {
            float lo, hi;
            UNPACK2(lo, hi, acc2[i][j]);
            accf[i][2 * j] = lo * inv;
            accf[i][2 * j + 1] = hi * inv;
        }
    }

    float* osh = (float*)&sm.v[0][0][0][0];
    if (p_hh == 0) {
#pragma unroll
        for (int i = 0; i < 8; i++)
#pragma unroll
            for (int j = 0; j < 8; j++)
                osh[(r0 + i) * VP + (c0 + j)] = accf[i][j];
    }
    if (t < 64) osh[x_r * VP + 128] = acc128 * (0.5f / sm.rsum[0][x_r]);
    __syncthreads();
    if (p_hh == 1) {
#pragma unroll
        for (int i = 0; i < 8; i++)
#pragma unroll
            for (int j = 0; j < 8; j++)
                osh[(r0 + i) * VP + (c0 + j)] += accf[i][j];
    }
    if (t >= 64 && t < 128) osh[x_r * VP + 128] += acc128 * (0.5f / sm.rsum[1][x_r]);
    __syncthreads();

    for (int idx = t; idx < RT * Cc; idx += 256) {
        int r = idx / Cc, c = idx % Cc;
        g_comb[(b * Nn + row0 + r) * VP + c] = osh[r * VP + c];
    }
}

// =================== 3a) gates r, u, cand_x (2 CTA/SM) ===================
struct GateASmem {
    float sel[Cc][68];
    float qv[Qq][64];
    float W[2][Cc][64];
    int   nodes[64];
};

__global__ void __launch_bounds__(256, 2) gateA_kernel(
    const float* __restrict__ qv_g, const int* __restrict__ nodes,
    const float* __restrict__ x_g, const float* __restrict__ h_g,
    const float* __restrict__ W_r, const float* __restrict__ b_r,
    const float* __restrict__ W_u, const float* __restrict__ b_u,
    const float* __restrict__ W_c, const float* __restrict__ b_c) {
    extern __shared__ char sm_raw[];
    GateASmem& sm = *reinterpret_cast<GateASmem*>(sm_raw);
    const int t = threadIdx.x;
    const int k0 = blockIdx.x * 64;
    const int g = blockIdx.y;
    const float* W    = (g == 0) ? W_r : (g == 1) ? W_u : W_c;
    const float* bias = (g == 0) ? b_r : (g == 1) ? b_u : b_c;
    const int CN = (g == 2) ? 65 : Cc;
    const int NCH = CN * 16;

    if (t < 64) sm.nodes[t] = nodes[k0 + t];
    __syncthreads();
    if (g == 2) {
        for (int idx = t; idx < 64 * 65; idx += 256) {
            int r = idx / 65, c = idx % 65;
            sm.sel[c][r] = x_g[sm.nodes[r] * 65 + c];
        }
    } else {
        for (int idx = t; idx < 64 * Cc; idx += 256) {
            int r = idx / Cc, c = idx % Cc;
            sm.sel[c][r] = g_comb[sm.nodes[r] * VP + c];
        }
    }
    for (int idx = t; idx < 64 * Qq; idx += 256) {
        int r = idx / Qq, q = idx % Qq;
        sm.qv[q][r] = qv_g[(k0 + r) * Qq + q];
    }
    for (int idx = t; idx < NCH; idx += 256)
        cp16(&sm.W[0][idx / 16][(idx % 16) * 4], &W[(idx / 16) * 64 + (idx % 16) * 4]);
    cp_commit();

    const int rg = t >> 4, og = t & 15;
    const int r0 = rg * 4, o0 = og * 4;
    u64t acc2[4][2];
#pragma unroll
    for (int i = 0; i < 4; i++) { acc2[i][0] = 0ull; acc2[i][1] = 0ull; }

    for (int q = 0; q < Qq; q++) {
        const int buf = q & 1;
        if (q + 1 < Qq) {
            for (int idx = t; idx < NCH; idx += 256)
                cp16(&sm.W[buf ^ 1][idx / 16][(idx % 16) * 4],
                     &W[((q + 1) * Cc + idx / 16) * 64 + (idx % 16) * 4]);
        }
        cp_commit();
        cp_wait<1>();
        __syncthreads();

        u64t a2[4][2];
#pragma unroll
        for (int i = 0; i < 4; i++) { a2[i][0] = 0ull; a2[i][1] = 0ull; }
        for (int c = 0; c < CN; c++) {
            float4 a = *(const float4*)&sm.sel[c][r0];
            float4 w = *(const float4*)&sm.W[buf][c][o0];
            u64t wv0, wv1;
            PACK2(wv0, w.x, w.y); PACK2(wv1, w.z, w.w);
            float av[4] = {a.x, a.y, a.z, a.w};
#pragma unroll
            for (int i = 0; i < 4; i++) {
                u64t ad; PACK2(ad, av[i], av[i]);
                FMA2(a2[i][0], ad, wv0, a2[i][0]);
                FMA2(a2[i][1], ad, wv1, a2[i][1]);
            }
        }
        float4 qq = *(const float4*)&sm.qv[q][r0];
        float qvv[4] = {qq.x, qq.y, qq.z, qq.w};
#pragma unroll
        for (int i = 0; i < 4; i++) {
            u64t qd; PACK2(qd, qvv[i], qvv[i]);
            FMA2(acc2[i][0], qd, a2[i][0], acc2[i][0]);
            FMA2(acc2[i][1], qd, a2[i][1], acc2[i][1]);
        }
        __syncthreads();
    }

    float acc[4][4];
#pragma unroll
    for (int i = 0; i < 4; i++) {
        UNPACK2(acc[i][0], acc[i][1], acc2[i][0]);
        UNPACK2(acc[i][2], acc[i][3], acc2[i][1]);
    }
    for (int q = 0; q < Qq; q++) {
        float4 bb = *(const float4*)&bias[q * 64 + o0];
        float bv4[4] = {bb.x, bb.y, bb.z, bb.w};
        float4 qq = *(const float4*)&sm.qv[q][r0];
        float qvv[4] = {qq.x, qq.y, qq.z, qq.w};
#pragma unroll
        for (int i = 0; i < 4; i++)
#pragma unroll
            for (int j = 0; j < 4; j++) acc[i][j] += qvv[i] * bv4[j];
    }
#pragma unroll
    for (int i = 0; i < 4; i++) {
        int kidx = k0 + r0 + i;
#pragma unroll
        for (int j = 0; j < 4; j++) {
            int o = o0 + j;
            if (g == 0) {
                float z = 1.f / (1.f + __expf(-acc[i][j]));
                g_hsel[kidx * 64 + o] = z * h_g[sm.nodes[r0 + i] * 64 + o];
            } else if (g == 1) {
                g_u[kidx * 64 + o] = 1.f / (1.f + __expf(-acc[i][j]));
            } else {
                g_cx[kidx * 64 + o] = acc[i][j];
            }
        }
    }
}

// =================== 3b) cand h-part + final combine ===================
struct GateBSmem {
    float sel[64][68];
    float qv[Qq][64];
    float W[2][64][64];
};

__global__ void __launch_bounds__(256, 2) gateB_kernel(
    const float* __restrict__ qv_g, const float* __restrict__ W_c,
    float* __restrict__ out) {
    extern __shared__ char sm_raw[];
    GateBSmem& sm = *reinterpret_cast<GateBSmem*>(sm_raw);
    const int t = threadIdx.x;
    const int k0 = blockIdx.x * 64;

    for (int idx = t; idx < 64 * 64; idx += 256) {
        int r = idx / 64, c = idx % 64;
        sm.sel[c][r] = g_hsel[(k0 + r) * 64 + c];
    }
    for (int idx = t; idx < 64 * Qq; idx += 256) {
        int r = idx / Qq, q = idx % Qq;
        sm.qv[q][r] = qv_g[(k0 + r) * Qq + q];
    }
    for (int idx = t; idx < 64 * 16; idx += 256)
        cp16(&sm.W[0][idx / 16][(idx % 16) * 4],
             &W_c[(65 + idx / 16) * 64 + (idx % 16) * 4]);
    cp_commit();

    const int rg = t >> 4, og = t & 15;
    const int r0 = rg * 4, o0 = og * 4;
    u64t acc2[4][2];
#pragma unroll
    for (int i = 0; i < 4; i++) { acc2[i][0] = 0ull; acc2[i][1] = 0ull; }

    for (int q = 0; q < Qq; q++) {
        const int buf = q & 1;
        if (q + 1 < Qq) {
            for (int idx = t; idx < 64 * 16; idx += 256)
                cp16(&sm.W[buf ^ 1][idx / 16][(idx % 16) * 4],
                     &W_c[((q + 1) * Cc + 65 + idx / 16) * 64 + (idx % 16) * 4]);
        }
        cp_commit();
        cp_wait<1>();
        __syncthreads();

        u64t a2[4][2];
#pragma unroll
        for (int i = 0; i < 4; i++) { a2[i][0] = 0ull; a2[i][1] = 0ull; }
        for (int c = 0; c < 64; c++) {
            float4 a = *(const float4*)&sm.sel[c][r0];
            float4 w = *(const float4*)&sm.W[buf][c][o0];
            u64t wv0, wv1;
            PACK2(wv0, w.x, w.y); PACK2(wv1, w.z, w.w);
            float av[4] = {a.x, a.y, a.z, a.w};
#pragma unroll
            for (int i = 0; i < 4; i++) {
                u64t ad; PACK2(ad, av[i], av[i]);
                FMA2(a2[i][0], ad, wv0, a2[i][0]);
                FMA2(a2[i][1], ad, wv1, a2[i][1]);
            }
        }
        float4 qq = *(const float4*)&sm.qv[q][r0];
        float qvv[4] = {qq.x, qq.y, qq.z, qq.w};
#pragma unroll
        for (int i = 0; i < 4; i++) {
            u64t qd; PACK2(qd, qvv[i], qvv[i]);
            FMA2(acc2[i][0], qd, a2[i][0], acc2[i][0]);
            FMA2(acc2[i][1], qd, a2[i][1], acc2[i][1]);
        }
        __syncthreads();
    }

    float acc[4][4];
#pragma unroll
    for (int i = 0; i < 4; i++) {
        UNPACK2(acc[i][0], acc[i][1], acc2[i][0]);
        UNPACK2(acc[i][2], acc[i][3], acc2[i][1]);
    }
#pragma unroll
    for (int i = 0; i < 4; i++) {
        int kidx = k0 + r0 + i;
#pragma unroll
        for (int j = 0; j < 4; j++) {
            int o = o0 + j;
            float raw = g_cx[kidx * 64 + o] + acc[i][j];
            float cand = tanhf(raw);
            float u  = g_u[kidx * 64 + o];
            float hs = g_hsel[kidx * 64 + o];
            out[kidx * 64 + o] = (1.f - u) * hs + u * cand;
        }
    }
}

// =================== launch ===================
extern "C" void kernel_launch(void* const* d_in, const int* in_sizes, int n_in,
                              void* d_out, int out_size) {
    const float* x   = (const float*)d_in[0];
    const float* h   = (const float*)d_in[1];
    const float* qv  = (const float*)d_in[2];
    const int*   adj = (const int*)d_in[3];
    const int*   nodes = (const int*)d_in[4];
    const float* Wq = (const float*)d_in[5];
    const float* bq = (const float*)d_in[6];
    const float* Wk = (const float*)d_in[7];
    const float* bk = (const float*)d_in[8];
    const float* Wv = (const float*)d_in[9];
    const float* bv = (const float*)d_in[10];
    const float* W_r = (const float*)d_in[11];
    const float* b_r = (const float*)d_in[12];
    const float* W_u = (const float*)d_in[13];
    const float* b_u = (const float*)d_in[14];
    const float* W_c = (const float*)d_in[15];
    const float* b_c = (const float*)d_in[16];
    float* out = (float*)d_out;

    cudaFuncSetAttribute(proj_kernel, cudaFuncAttributeMaxDynamicSharedMemorySize, (int)sizeof(ProjSmem));
    cudaFuncSetAttribute(attn_kernel, cudaFuncAttributeMaxDynamicSharedMemorySize, (int)sizeof(AttnSmem));
    cudaFuncSetAttribute(gateA_kernel, cudaFuncAttributeMaxDynamicSharedMemorySize, (int)sizeof(GateASmem));
    cudaFuncSetAttribute(gateB_kernel, cudaFuncAttributeMaxDynamicSharedMemorySize, (int)sizeof(GateBSmem));

    flag_zero_kernel<<<1, 256>>>();
    flag_mark_kernel<<<Kk / 256, 256>>>(nodes);
    proj_kernel<<<dim3(NROW / 32, 3), 256, sizeof(ProjSmem)>>>(x, h, Wq, bq, Wk, bk, Wv, bv);
    attn_kernel<<<dim3(Nn / RT, Bb), 256, sizeof(AttnSmem)>>>(adj);
    gateA_kernel<<<dim3(Kk / 64, 3), 256, sizeof(GateASmem)>>>(qv, nodes, x, h,
                                                               W_r, b_r, W_u, b_u, W_c, b_c);
    gateB_kernel<<<dim3(Kk / 64, 1), 256, sizeof(GateBSmem)>>>(qv, W_c, out);
}

// round 8
// speedup vs baseline: 1.4873x; 1.1124x over previous
#include <cuda_runtime.h>
#include <math.h>

#define Hh 2
#define Bb 8
#define Nn 2048
#define Dd 64
#define Qq 16
#define Cc 129
#define C8v 16
#define Kk 8192
#define VP 136   // padded stride (mma n-tiles: 17 x 8 = 136)
#define NEGV (-9.0e15f)
#define NROW (Bb*Nn)
#define RT 64
#define MT 64
#define NTILE (Nn/MT)
#define NT_C 17  // n-tiles over 136 cols

// ---------------- packed f32x2 helpers (Blackwell) ----------------
typedef unsigned long long u64t;
#define PACK2(out, lo, hi) \
    asm("mov.b64 %0, {%1, %2};" : "=l"(out) : "f"(lo), "f"(hi))
#define UNPACK2(lo, hi, in) \
    asm("mov.b64 {%0, %1}, %2;" : "=f"(lo), "=f"(hi) : "l"(in))
#define FMA2(d, a, b, c) \
    asm("fma.rn.f32x2 %0, %1, %2, %3;" : "=l"(d) : "l"(a), "l"(b), "l"(c))
#define MUL2(d, a, b) \
    asm("mul.rn.f32x2 %0, %1, %2;" : "=l"(d) : "l"(a), "l"(b))

// tf32 helpers
#define CVT_TF32(u, f) asm("cvt.rna.tf32.f32 %0, %1;" : "=r"(u) : "f"(f))
#define MMA_TF32(c0,c1,c2,c3, a0,a1,a2,a3, b0,b1) \
    asm volatile("mma.sync.aligned.m16n8k8.row.col.f32.tf32.tf32.f32 " \
        "{%0,%1,%2,%3}, {%4,%5,%6,%7}, {%8,%9}, {%0,%1,%2,%3};" \
        : "+f"(c0), "+f"(c1), "+f"(c2), "+f"(c3) \
        : "r"(a0), "r"(a1), "r"(a2), "r"(a3), "r"(b0), "r"(b1))

// ---------------- device scratch ----------------
__device__ float g_q[Hh*NROW*C8v];
__device__ float g_k[Hh*NROW*C8v];
__device__ float g_v[Hh*NROW*VP];
__device__ float g_comb[NROW*VP];
__device__ float g_u[Kk*Dd];
__device__ float g_hsel[Kk*Dd];
__device__ float g_cx[Kk*Dd];
__device__ int   g_batch_flag[Bb];
__device__ int   g_tile_flag[NROW/RT];

// ---------------- cp.async helpers ----------------
__device__ __forceinline__ unsigned smem_u32(const void* p) {
    return (unsigned)__cvta_generic_to_shared(p);
}
__device__ __forceinline__ void cp16(void* dst, const void* src) {
    asm volatile("cp.async.cg.shared.global [%0], [%1], 16;\n"
                 :: "r"(smem_u32(dst)), "l"(src));
}
__device__ __forceinline__ void cp_commit() { asm volatile("cp.async.commit_group;\n"); }
template<int N> __device__ __forceinline__ void cp_wait() {
    asm volatile("cp.async.wait_group %0;\n" :: "n"(N));
}

// ---------------- flags ----------------
__global__ void flag_zero_kernel() {
    int t = threadIdx.x;
    if (t < Bb) g_batch_flag[t] = 0;
    for (int i = t; i < NROW/RT; i += 256) g_tile_flag[i] = 0;
}
__global__ void flag_mark_kernel(const int* __restrict__ nodes) {
    int i = blockIdx.x * 256 + threadIdx.x;
    if (i < Kk) {
        int row = nodes[i];
        g_tile_flag[row >> 6] = 1;
        g_batch_flag[row >> 11] = 1;
    }
}

// =================== 1) QKV projection ===================
struct ProjSmem {
    float comb[Cc][36];
    float W[Cc][VP];
    float bias[VP];
};

__global__ void proj_kernel(const float* __restrict__ x, const float* __restrict__ h,
                            const float* __restrict__ Wq, const float* __restrict__ bq,
                            const float* __restrict__ Wk, const float* __restrict__ bk,
                            const float* __restrict__ Wv, const float* __restrict__ bv) {
    extern __shared__ char sm_raw[];
    ProjSmem& sm = *reinterpret_cast<ProjSmem*>(sm_raw);
    const int t = threadIdx.x;
    const int row0 = blockIdx.x * 32;
    if (!g_batch_flag[row0 >> 11]) return;
    const int y = blockIdx.y;

    for (int idx = t; idx < 32 * Cc; idx += 256) {
        int r = idx / Cc, c = idx % Cc;
        int row = row0 + r;
        float v = (c < 65) ? x[row * 65 + c] : h[row * 64 + (c - 65)];
        sm.comb[c][r] = v;
    }
    if (y == 0) {
        for (int idx = t; idx < Cc * 64; idx += 256) {
            int c = idx / 64, o = idx % 64;
            float w;
            if (o < 32)      w = Wq[((o >> 4) * Cc + c) * C8v + (o & 15)];
            else { int o2 = o - 32; w = Wk[((o2 >> 4) * Cc + c) * C8v + (o2 & 15)]; }
            sm.W[c][o] = w;
        }
        if (t < 64) {
            float b;
            if (t < 32)      b = bq[(t >> 4) * C8v + (t & 15)];
            else { int o2 = t - 32; b = bk[(o2 >> 4) * C8v + (o2 & 15)]; }
            sm.bias[t] = b;
        }
    } else {
        int hh = y - 1;
        for (int idx = t; idx < Cc * VP; idx += 256) {
            int c = idx / VP, o = idx % VP;
            sm.W[c][o] = (o < Cc) ? Wv[(hh * Cc + c) * Cc + o] : 0.f;
        }
        for (int o = t; o < VP; o += 256) sm.bias[o] = (o < Cc) ? bv[hh * Cc + o] : 0.f;
    }
    __syncthreads();

    if (y == 0) {
        int r = t >> 3, og = t & 7;
        int c0 = og * 8;
        float acc[8];
#pragma unroll
        for (int j = 0; j < 8; j++) acc[j] = 0.f;
        for (int c = 0; c < Cc; c++) {
            float a = sm.comb[c][r];
#pragma unroll
            for (int j = 0; j < 8; j++) acc[j] += a * sm.W[c][c0 + j];
        }
        int row = row0 + r;
#pragma unroll
        for (int j = 0; j < 8; j++) {
            int o = c0 + j;
            float val = acc[j] + sm.bias[o];
            if (o < 32) {
                g_q[(((o >> 4) * NROW) + row) * C8v + (o & 15)] = val;
            } else {
                int o2 = o - 32;
                g_k[(((o2 >> 4) * NROW) + row) * C8v + (o2 & 15)] = val;
            }
        }
    } else {
        int hh = y - 1;
        int r = t >> 3, og = t & 7;
        int c0 = og * 16;
        int xcol = 128 + og;   // og 0..7 covers cols 128..135 (zeros beyond 128)
        float acc[17];
#pragma unroll
        for (int j = 0; j < 17; j++) acc[j] = 0.f;
        for (int c = 0; c < Cc; c++) {
            float a = sm.comb[c][r];
#pragma unroll
            for (int j = 0; j < 16; j++) acc[j] += a * sm.W[c][c0 + j];
            acc[16] += a * sm.W[c][xcol];
        }
        int row = row0 + r;
        float* dst = &g_v[((hh * NROW) + row) * VP];
#pragma unroll
        for (int j = 0; j < 16; j++) dst[c0 + j] = acc[j] + sm.bias[c0 + j];
        dst[xcol] = acc[16] + sm.bias[xcol];
    }
}

// =================== 2) attention: scalar QK + softmax, 3xTF32 mma PV ===================
struct AttnSmem {
    float v[2][Hh][MT][VP];      // 139264 B (VP=136, cols>=129 zero)
    float k[2][Hh][MT][C8v];     //  16384 B
    int   adj[2][RT][68];        //  34816 B
    float p[Hh][MT][RT];         //  32768 B  (= A^T for mma)
    float rmax[Hh][RT];
    float rsum[Hh][RT];
    float fac[Hh][RT];
};                               // ~224 KB

__device__ __forceinline__ void attn_prefetch(AttnSmem& sm, int buf, int b, int row0,
                                              int m0, const int* __restrict__ adjg, int t) {
    for (int idx = t; idx < Hh * MT * 34; idx += 256) {
        int h_ = idx / (MT * 34), rem = idx % (MT * 34), m = rem / 34, c4 = rem % 34;
        cp16(&sm.v[buf][h_][m][c4 * 4],
             &g_v[((h_ * NROW) + b * Nn + m0 + m) * VP + c4 * 4]);
    }
    for (int idx = t; idx < Hh * MT * 4; idx += 256) {
        int h_ = idx / (MT * 4), rem = idx % (MT * 4), m = rem >> 2, d4 = rem & 3;
        cp16(&sm.k[buf][h_][m][d4 * 4],
             &g_k[((h_ * NROW) + b * Nn + m0 + m) * C8v + d4 * 4]);
    }
    for (int idx = t; idx < RT * 16; idx += 256) {
        int r = idx >> 4, c4 = idx & 15;
        cp16(&sm.adj[buf][r][c4 * 4],
             &adjg[(b * Nn + row0 + r) * Nn + m0 + c4 * 4]);
    }
}

__global__ void __launch_bounds__(256, 1) attn_kernel(const int* __restrict__ adjg) {
    extern __shared__ char sm_raw[];
    AttnSmem& sm = *reinterpret_cast<AttnSmem*>(sm_raw);
    const int t = threadIdx.x;
    const int b = blockIdx.y;
    const int row0 = blockIdx.x * RT;
    if (!g_tile_flag[(b * Nn + row0) >> 6]) return;

    // scores/softmax mapping (unchanged)
    const int s_hh = t >> 7, s_r = (t & 127) >> 1, s_half = t & 1;
    // mma mapping
    const int warp = t >> 5, lane = t & 31;
    const int m_h = warp >> 2;        // head
    const int m_R0 = (warp & 3) * 16; // row group base
    const int gid = lane >> 2, tg = lane & 3;
    const int x_hh = t >> 6, x_r = t & 63;

    float qreg[16];
    {
        const float4* qsrc = (const float4*)&g_q[((s_hh * NROW) + b * Nn + row0 + s_r) * C8v];
#pragma unroll
        for (int j = 0; j < 4; j++) {
            float4 qq = qsrc[j];
            qreg[4 * j] = qq.x; qreg[4 * j + 1] = qq.y;
            qreg[4 * j + 2] = qq.z; qreg[4 * j + 3] = qq.w;
        }
    }
    if (t < 128) { sm.rmax[x_hh][x_r] = -INFINITY; sm.rsum[x_hh][x_r] = 0.f; }

    float acc[NT_C][4];
#pragma unroll
    for (int n = 0; n < NT_C; n++)
#pragma unroll
        for (int j = 0; j < 4; j++) acc[n][j] = 0.f;

    attn_prefetch(sm, 0, b, row0, 0, adjg, t);
    cp_commit();

    for (int mt = 0; mt < NTILE; mt++) {
        const int buf = mt & 1;
        if (mt + 1 < NTILE) attn_prefetch(sm, buf ^ 1, b, row0, (mt + 1) * MT, adjg, t);
        cp_commit();
        cp_wait<1>();
        __syncthreads();

        // ---- scores (scalar, unchanged) ----
        {
#pragma unroll 4
            for (int i = 0; i < 32; i++) {
                int m = s_half * 32 + i;
                const float4* k4 = (const float4*)&sm.k[buf][s_hh][m][0];
                float s = 0.f;
#pragma unroll
                for (int d4 = 0; d4 < 4; d4++) {
                    float4 kk = k4[d4];
                    s += qreg[4 * d4] * kk.x + qreg[4 * d4 + 1] * kk.y
                       + qreg[4 * d4 + 2] * kk.z + qreg[4 * d4 + 3] * kk.w;
                }
                s *= 0.25f;
                s = (s > 0.f) ? s : 0.2f * s;
                if (sm.adj[buf][s_r][m] == 0) s = NEGV;
                sm.p[s_hh][m][s_r] = s;
            }
        }
        __syncthreads();

        // ---- online softmax (unchanged) ----
        {
            int pr = t >> 1;
            int ph = pr >> 6, rr = pr & 63, hf = t & 1;
            float tmax = -INFINITY;
#pragma unroll 4
            for (int j = 0; j < 32; j++)
                tmax = fmaxf(tmax, sm.p[ph][hf * 32 + j][rr]);
            tmax = fmaxf(tmax, __shfl_xor_sync(0xffffffffu, tmax, 1));
            float oldmax = sm.rmax[ph][rr];
            float nmax = fmaxf(oldmax, tmax);
            float ssum = 0.f;
#pragma unroll 4
            for (int j = 0; j < 32; j++) {
                int m = hf * 32 + j;
                float e = __expf(sm.p[ph][m][rr] - nmax);
                sm.p[ph][m][rr] = e;
                ssum += e;
            }
            ssum += __shfl_xor_sync(0xffffffffu, ssum, 1);
            if (hf == 0) {
                float f = __expf(oldmax - nmax);
                sm.fac[ph][rr] = f;
                sm.rsum[ph][rr] = sm.rsum[ph][rr] * f + ssum;
                sm.rmax[ph][rr] = nmax;
            }
        }
        __syncthreads();

        // ---- PV via mma m16n8k8 tf32 (3xTF32 split) ----
        {
            float f0 = sm.fac[m_h][m_R0 + gid];
            float f1 = sm.fac[m_h][m_R0 + gid + 8];
#pragma unroll
            for (int n = 0; n < NT_C; n++) {
                acc[n][0] *= f0; acc[n][1] *= f0;
                acc[n][2] *= f1; acc[n][3] *= f1;
            }
#pragma unroll
            for (int ks = 0; ks < 8; ks++) {
                const int kk = ks * 8;
                // A fragment: A[row][k] = P[row=query][key] = sm.p[key][query]
                float a0f = sm.p[m_h][kk + tg][m_R0 + gid];
                float a1f = sm.p[m_h][kk + tg][m_R0 + gid + 8];
                float a2f = sm.p[m_h][kk + tg + 4][m_R0 + gid];
                float a3f = sm.p[m_h][kk + tg + 4][m_R0 + gid + 8];
                unsigned ah0, ah1, ah2, ah3, al0, al1, al2, al3;
                CVT_TF32(ah0, a0f); CVT_TF32(ah1, a1f);
                CVT_TF32(ah2, a2f); CVT_TF32(ah3, a3f);
                float r0f = a0f - __uint_as_float(ah0);
                float r1f = a1f - __uint_as_float(ah1);
                float r2f = a2f - __uint_as_float(ah2);
                float r3f = a3f - __uint_as_float(ah3);
                CVT_TF32(al0, r0f); CVT_TF32(al1, r1f);
                CVT_TF32(al2, r2f); CVT_TF32(al3, r3f);

                const float* vb = &sm.v[buf][m_h][0][0];
#pragma unroll
                for (int n = 0; n < NT_C; n++) {
                    float b0f = vb[(kk + tg) * VP + n * 8 + gid];
                    float b1f = vb[(kk + tg + 4) * VP + n * 8 + gid];
                    unsigned bh0, bh1, bl0, bl1;
                    CVT_TF32(bh0, b0f); CVT_TF32(bh1, b1f);
                    float s0f = b0f - __uint_as_float(bh0);
                    float s1f = b1f - __uint_as_float(bh1);
                    CVT_TF32(bl0, s0f); CVT_TF32(bl1, s1f);
                    MMA_TF32(acc[n][0], acc[n][1], acc[n][2], acc[n][3],
                             ah0, ah1, ah2, ah3, bh0, bh1);
                    MMA_TF32(acc[n][0], acc[n][1], acc[n][2], acc[n][3],
                             ah0, ah1, ah2, ah3, bl0, bl1);
                    MMA_TF32(acc[n][0], acc[n][1], acc[n][2], acc[n][3],
                             al0, al1, al2, al3, bh0, bh1);
                }
            }
        }
        __syncthreads();
    }

    // ---- finalize: mean over heads via osh (reuse v region) ----
    float inv0 = 0.5f / sm.rsum[m_h][m_R0 + gid];
    float inv1 = 0.5f / sm.rsum[m_h][m_R0 + gid + 8];
    float* osh = (float*)&sm.v[0][0][0][0];   // 64 x VP floats
    const int ra = m_R0 + gid, rb = m_R0 + gid + 8;
    if (m_h == 0) {
#pragma unroll
        for (int n = 0; n < NT_C; n++) {
            int cbase = n * 8 + 2 * tg;
            osh[ra * VP + cbase]     = acc[n][0] * inv0;
            osh[ra * VP + cbase + 1] = acc[n][1] * inv0;
            osh[rb * VP + cbase]     = acc[n][2] * inv1;
            osh[rb * VP + cbase + 1] = acc[n][3] * inv1;
        }
    }
    __syncthreads();
    if (m_h == 1) {
#pragma unroll
        for (int n = 0; n < NT_C; n++) {
            int cbase = n * 8 + 2 * tg;
            osh[ra * VP + cbase]     += acc[n][0] * inv0;
            osh[ra * VP + cbase + 1] += acc[n][1] * inv0;
            osh[rb * VP + cbase]     += acc[n][2] * inv1;
            osh[rb * VP + cbase + 1] += acc[n][3] * inv1;
        }
    }
    __syncthreads();

    for (int idx = t; idx < RT * Cc; idx += 256) {
        int r = idx / Cc, c = idx % Cc;
        g_comb[(b * Nn + row0 + r) * VP + c] = osh[r * VP + c];
    }
}

// =================== 3a) gates r, u, cand_x ===================
struct GateASmem {
    float sel[Cc][68];
    float qv[Qq][64];
    float W[2][Cc][64];
    int   nodes[64];
};

__global__ void __launch_bounds__(256, 2) gateA_kernel(
    const float* __restrict__ qv_g, const int* __restrict__ nodes,
    const float* __restrict__ x_g, const float* __restrict__ h_g,
    const float* __restrict__ W_r, const float* __restrict__ b_r,
    const float* __restrict__ W_u, const float* __restrict__ b_u,
    const float* __restrict__ W_c, const float* __restrict__ b_c) {
    extern __shared__ char sm_raw[];
    GateASmem& sm = *reinterpret_cast<GateASmem*>(sm_raw);
    const int t = threadIdx.x;
    const int k0 = blockIdx.x * 64;
    const int g = blockIdx.y;
    const float* W    = (g == 0) ? W_r : (g == 1) ? W_u : W_c;
    const float* bias = (g == 0) ? b_r : (g == 1) ? b_u : b_c;
    const int CN = (g == 2) ? 65 : Cc;
    const int NCH = CN * 16;

    if (t < 64) sm.nodes[t] = nodes[k0 + t];
    __syncthreads();
    if (g == 2) {
        for (int idx = t; idx < 64 * 65; idx += 256) {
            int r = idx / 65, c = idx % 65;
            sm.sel[c][r] = x_g[sm.nodes[r] * 65 + c];
        }
    } else {
        for (int idx = t; idx < 64 * Cc; idx += 256) {
            int r = idx / Cc, c = idx % Cc;
            sm.sel[c][r] = g_comb[sm.nodes[r] * VP + c];
        }
    }
    for (int idx = t; idx < 64 * Qq; idx += 256) {
        int r = idx / Qq, q = idx % Qq;
        sm.qv[q][r] = qv_g[(k0 + r) * Qq + q];
    }
    for (int idx = t; idx < NCH; idx += 256)
        cp16(&sm.W[0][idx / 16][(idx % 16) * 4], &W[(idx / 16) * 64 + (idx % 16) * 4]);
    cp_commit();

    const int rg = t >> 4, og = t & 15;
    const int r0 = rg * 4, o0 = og * 4;
    u64t acc2[4][2];
#pragma unroll
    for (int i = 0; i < 4; i++) { acc2[i][0] = 0ull; acc2[i][1] = 0ull; }

    for (int q = 0; q < Qq; q++) {
        const int buf = q & 1;
        if (q + 1 < Qq) {
            for (int idx = t; idx < NCH; idx += 256)
                cp16(&sm.W[buf ^ 1][idx / 16][(idx % 16) * 4],
                     &W[((q + 1) * Cc + idx / 16) * 64 + (idx % 16) * 4]);
        }
        cp_commit();
        cp_wait<1>();
        __syncthreads();

        u64t a2[4][2];
#pragma unroll
        for (int i = 0; i < 4; i++) { a2[i][0] = 0ull; a2[i][1] = 0ull; }
        for (int c = 0; c < CN; c++) {
            float4 a = *(const float4*)&sm.sel[c][r0];
            float4 w = *(const float4*)&sm.W[buf][c][o0];
            u64t wv0, wv1;
            PACK2(wv0, w.x, w.y); PACK2(wv1, w.z, w.w);
            float av[4] = {a.x, a.y, a.z, a.w};
#pragma unroll
            for (int i = 0; i < 4; i++) {
                u64t ad; PACK2(ad, av[i], av[i]);
                FMA2(a2[i][0], ad, wv0, a2[i][0]);
                FMA2(a2[i][1], ad, wv1, a2[i][1]);
            }
        }
        float4 qq = *(const float4*)&sm.qv[q][r0];
        float qvv[4] = {qq.x, qq.y, qq.z, qq.w};
#pragma unroll
        for (int i = 0; i < 4; i++) {
            u64t qd; PACK2(qd, qvv[i], qvv[i]);
            FMA2(acc2[i][0], qd, a2[i][0], acc2[i][0]);
            FMA2(acc2[i][1], qd, a2[i][1], acc2[i][1]);
        }
        __syncthreads();
    }

    float acc[4][4];
#pragma unroll
    for (int i = 0; i < 4; i++) {
        UNPACK2(acc[i][0], acc[i][1], acc2[i][0]);
        UNPACK2(acc[i][2], acc[i][3], acc2[i][1]);
    }
    for (int q = 0; q < Qq; q++) {
        float4 bb = *(const float4*)&bias[q * 64 + o0];
        float bv4[4] = {bb.x, bb.y, bb.z, bb.w};
        float4 qq = *(const float4*)&sm.qv[q][r0];
        float qvv[4] = {qq.x, qq.y, qq.z, qq.w};
#pragma unroll
        for (int i = 0; i < 4; i++)
#pragma unroll
            for (int j = 0; j < 4; j++) acc[i][j] += qvv[i] * bv4[j];
    }
#pragma unroll
    for (int i = 0; i < 4; i++) {
        int kidx = k0 + r0 + i;
#pragma unroll
        for (int j = 0; j < 4; j++) {
            int o = o0 + j;
            if (g == 0) {
                float z = 1.f / (1.f + __expf(-acc[i][j]));
                g_hsel[kidx * 64 + o] = z * h_g[sm.nodes[r0 + i] * 64 + o];
            } else if (g == 1) {
                g_u[kidx * 64 + o] = 1.f / (1.f + __expf(-acc[i][j]));
            } else {
                g_cx[kidx * 64 + o] = acc[i][j];
            }
        }
    }
}

// =================== 3b) cand h-part + final combine ===================
struct GateBSmem {
    float sel[64][68];
    float qv[Qq][64];
    float W[2][64][64];
};

__global__ void __launch_bounds__(256, 2) gateB_kernel(
    const float* __restrict__ qv_g, const float* __restrict__ W_c,
    float* __restrict__ out) {
    extern __shared__ char sm_raw[];
    GateBSmem& sm = *reinterpret_cast<GateBSmem*>(sm_raw);
    const int t = threadIdx.x;
    const int k0 = blockIdx.x * 64;

    for (int idx = t; idx < 64 * 64; idx += 256) {
        int r = idx / 64, c = idx % 64;
        sm.sel[c][r] = g_hsel[(k0 + r) * 64 + c];
    }
    for (int idx = t; idx < 64 * Qq; idx += 256) {
        int r = idx / Qq, q = idx % Qq;
        sm.qv[q][r] = qv_g[(k0 + r) * Qq + q];
    }
    for (int idx = t; idx < 64 * 16; idx += 256)
        cp16(&sm.W[0][idx / 16][(idx % 16) * 4],
             &W_c[(65 + idx / 16) * 64 + (idx % 16) * 4]);
    cp_commit();

    const int rg = t >> 4, og = t & 15;
    const int r0 = rg * 4, o0 = og * 4;
    u64t acc2[4][2];
#pragma unroll
    for (int i = 0; i < 4; i++) { acc2[i][0] = 0ull; acc2[i][1] = 0ull; }

    for (int q = 0; q < Qq; q++) {
        const int buf = q & 1;
        if (q + 1 < Qq) {
            for (int idx = t; idx < 64 * 16; idx += 256)
                cp16(&sm.W[buf ^ 1][idx / 16][(idx % 16) * 4],
                     &W_c[((q + 1) * Cc + 65 + idx / 16) * 64 + (idx % 16) * 4]);
        }
        cp_commit();
        cp_wait<1>();
        __syncthreads();

        u64t a2[4][2];
#pragma unroll
        for (int i = 0; i < 4; i++) { a2[i][0] = 0ull; a2[i][1] = 0ull; }
        for (int c = 0; c < 64; c++) {
            float4 a = *(const float4*)&sm.sel[c][r0];
            float4 w = *(const float4*)&sm.W[buf][c][o0];
            u64t wv0, wv1;
            PACK2(wv0, w.x, w.y); PACK2(wv1, w.z, w.w);
            float av[4] = {a.x, a.y, a.z, a.w};
#pragma unroll
            for (int i = 0; i < 4; i++) {
                u64t ad; PACK2(ad, av[i], av[i]);
                FMA2(a2[i][0], ad, wv0, a2[i][0]);
                FMA2(a2[i][1], ad, wv1, a2[i][1]);
            }
        }
        float4 qq = *(const float4*)&sm.qv[q][r0];
        float qvv[4] = {qq.x, qq.y, qq.z, qq.w};
#pragma unroll
        for (int i = 0; i < 4; i++) {
            u64t qd; PACK2(qd, qvv[i], qvv[i]);
            FMA2(acc2[i][0], qd, a2[i][0], acc2[i][0]);
            FMA2(acc2[i][1], qd, a2[i][1], acc2[i][1]);
        }
        __syncthreads();
    }

    float acc[4][4];
#pragma unroll
    for (int i = 0; i < 4; i++) {
        UNPACK2(acc[i][0], acc[i][1], acc2[i][0]);
        UNPACK2(acc[i][2], acc[i][3], acc2[i][1]);
    }
#pragma unroll
    for (int i = 0; i < 4; i++) {
        int kidx = k0 + r0 + i;
#pragma unroll
        for (int j = 0; j < 4; j++) {
            int o = o0 + j;
            float raw = g_cx[kidx * 64 + o] + acc[i][j];
            float cand = tanhf(raw);
            float u  = g_u[kidx * 64 + o];
            float hs = g_hsel[kidx * 64 + o];
            out[kidx * 64 + o] = (1.f - u) * hs + u * cand;
        }
    }
}

// =================== launch ===================
extern "C" void kernel_launch(void* const* d_in, const int* in_sizes, int n_in,
                              void* d_out, int out_size) {
    const float* x   = (const float*)d_in[0];
    const float* h   = (const float*)d_in[1];
    const float* qv  = (const float*)d_in[2];
    const int*   adj = (const int*)d_in[3];
    const int*   nodes = (const int*)d_in[4];
    const float* Wq = (const float*)d_in[5];
    const float* bq = (const float*)d_in[6];
    const float* Wk = (const float*)d_in[7];
    const float* bk = (const float*)d_in[8];
    const float* Wv = (const float*)d_in[9];
    const float* bv = (const float*)d_in[10];
    const float* W_r = (const float*)d_in[11];
    const float* b_r = (const float*)d_in[12];
    const float* W_u = (const float*)d_in[13];
    const float* b_u = (const float*)d_in[14];
    const float* W_c = (const float*)d_in[15];
    const float* b_c = (const float*)d_in[16];
    float* out = (float*)d_out;

    cudaFuncSetAttribute(proj_kernel, cudaFuncAttributeMaxDynamicSharedMemorySize, (int)sizeof(ProjSmem));
    cudaFuncSetAttribute(attn_kernel, cudaFuncAttributeMaxDynamicSharedMemorySize, (int)sizeof(AttnSmem));
    cudaFuncSetAttribute(gateA_kernel, cudaFuncAttributeMaxDynamicSharedMemorySize, (int)sizeof(GateASmem));
    cudaFuncSetAttribute(gateB_kernel, cudaFuncAttributeMaxDynamicSharedMemorySize, (int)sizeof(GateBSmem));

    flag_zero_kernel<<<1, 256>>>();
    flag_mark_kernel<<<Kk / 256, 256>>>(nodes);
    proj_kernel<<<dim3(NROW / 32, 3), 256, sizeof(ProjSmem)>>>(x, h, Wq, bq, Wk, bk, Wv, bv);
    attn_kernel<<<dim3(Nn / RT, Bb), 256, sizeof(AttnSmem)>>>(adj);
    gateA_kernel<<<dim3(Kk / 64, 3), 256, sizeof(GateASmem)>>>(qv, nodes, x, h,
                                                               W_r, b_r, W_u, b_u, W_c, b_c);
    gateB_kernel<<<dim3(Kk / 64, 1), 256, sizeof(GateBSmem)>>>(qv, W_c, out);
}